// round 13
// baseline (speedup 1.0000x reference)
#include <cuda_runtime.h>
#include <stdint.h>
#include <math.h>

#define N_NODES 100000
#define MEM_DIM 128
#define MSG_DIM 128

// ---------------- scratch (static device globals; no allocation) ----------------
__device__ float g_aggr[(size_t)N_NODES * MSG_DIM];
__device__ float g_cnt[N_NODES];
__device__ float g_newmem[(size_t)N_NODES * MEM_DIM]; // tf32-rounded at write
__device__ float g_memr[(size_t)N_NODES * MEM_DIM];   // tf32-rounded memory
__device__ float g_M[64 * 64];
__device__ float g_v[64];
__device__ float g_c0;
__device__ float g_Wg[256 * 512];  // gate-interleaved GRU weights (tf32)
__device__ float g_W1r[320 * 128]; // msg W1 tf32
__device__ float g_W2r[128 * 128]; // msg W2 tf32
__device__ float g_eW1r[192 * 64]; // emb W1 tf32

extern __shared__ float smem[];

// ---------------- helpers ----------------
__device__ __forceinline__ float to_tf32(float x) {
    unsigned int u;
    asm("cvt.rna.tf32.f32 %0, %1;" : "=r"(u) : "f"(x));
    return __uint_as_float(u);
}
__device__ __forceinline__ float4 to_tf32_4(float4 v) {
    v.x = to_tf32(v.x); v.y = to_tf32(v.y);
    v.z = to_tf32(v.z); v.w = to_tf32(v.w);
    return v;
}
__device__ __forceinline__ void mma_tf32(float4& c, const unsigned int a[4], const unsigned int b[2]) {
    asm volatile(
        "mma.sync.aligned.m16n8k8.row.col.f32.tf32.tf32.f32 "
        "{%0,%1,%2,%3},{%4,%5,%6,%7},{%8,%9},{%0,%1,%2,%3};\n"
        : "+f"(c.x), "+f"(c.y), "+f"(c.z), "+f"(c.w)
        : "r"(a[0]), "r"(a[1]), "r"(a[2]), "r"(a[3]), "r"(b[0]), "r"(b[1]));
}
__device__ __forceinline__ float sigm(float x) { return 1.f / (1.f + expf(-x)); }

__device__ __forceinline__ void cpa16(float* dst, const void* src, bool pred) {
    unsigned sa = (unsigned)__cvta_generic_to_shared(dst);
    asm volatile("cp.async.ca.shared.global [%0], [%1], 16, %2;\n"
                 :: "r"(sa), "l"(src), "r"(pred ? 16 : 0));
}
#define CP_COMMIT() asm volatile("cp.async.commit_group;\n" ::: "memory")
#define CP_WAIT(n)  asm volatile("cp.async.wait_group %0;\n" :: "n"(n) : "memory")

// ---------------- K-prep: zero + tf32 pre-round + GRU weight build ----------------
__global__ void k_prep(const float* __restrict__ memory,
                       const float* __restrict__ W1, const float* __restrict__ W2,
                       const float* __restrict__ eW1,
                       const float* __restrict__ Wih, const float* __restrict__ Whh) {
    size_t stride = (size_t)gridDim.x * blockDim.x;
    size_t t = (size_t)blockIdx.x * blockDim.x + threadIdx.x;
    float4 z = make_float4(0.f, 0.f, 0.f, 0.f);
    for (size_t i = t; i < (size_t)N_NODES * MSG_DIM / 4; i += stride) ((float4*)g_aggr)[i] = z;
    for (size_t i = t; i < N_NODES; i += stride) g_cnt[i] = 0.f;
    for (size_t i = t; i < (size_t)N_NODES * MEM_DIM / 4; i += stride)
        ((float4*)g_memr)[i] = to_tf32_4(__ldg((const float4*)memory + i));
    for (size_t i = t; i < 320 * 128 / 4; i += stride)
        ((float4*)g_W1r)[i] = to_tf32_4(__ldg((const float4*)W1 + i));
    for (size_t i = t; i < 128 * 128 / 4; i += stride)
        ((float4*)g_W2r)[i] = to_tf32_4(__ldg((const float4*)W2 + i));
    for (size_t i = t; i < 192 * 64 / 4; i += stride)
        ((float4*)g_eW1r)[i] = to_tf32_4(__ldg((const float4*)eW1 + i));
    for (size_t p = t; p < 256 * 512; p += stride) {
        int k = (int)(p >> 9), c = (int)(p & 511);
        int jb = c >> 5, tt = c & 31, q = tt >> 3;
        int j = jb * 8 + (tt & 7);
        float w;
        if (q == 0)      w = (k < 128) ? Wih[(size_t)j * 128 + k]
                                       : Whh[(size_t)j * 128 + (k - 128)];
        else if (q == 1) w = (k < 128) ? Wih[(size_t)(128 + j) * 128 + k]
                                       : Whh[(size_t)(128 + j) * 128 + (k - 128)];
        else if (q == 2) w = (k < 128) ? Wih[(size_t)(256 + j) * 128 + k] : 0.f;
        else             w = (k < 128) ? 0.f : Whh[(size_t)(256 + j) * 128 + (k - 128)];
        g_Wg[p] = to_tf32(w);
    }
}

// ---------------- K-pre: bilinear precompute for emb ----------------
__global__ void k_pre(const float* __restrict__ W2, const float* __restrict__ b2) {
    __shared__ float sW2[64 * 64];
    __shared__ float sb2[64];
    int tid = threadIdx.x;
    for (int i = tid; i < 64 * 64; i += 256) sW2[i] = W2[i];
    if (tid < 64) sb2[tid] = b2[tid];
    __syncthreads();
    for (int p = tid; p < 64 * 64; p += 256) {
        int j = p >> 6, k = p & 63;
        float s = 0.f;
        #pragma unroll 16
        for (int c = 0; c < 64; c++) s = fmaf(sW2[j * 64 + c], sW2[k * 64 + c], s);
        g_M[p] = s;
    }
    if (tid < 64) {
        float s = 0.f;
        #pragma unroll 16
        for (int c = 0; c < 64; c++) s = fmaf(sW2[tid * 64 + c], sb2[c], s);
        g_v[tid] = s;
    }
    if (tid == 0) {
        float s = 0.f;
        for (int c = 0; c < 64; c++) s = fmaf(sb2[c], sb2[c], s);
        g_c0 = s;
    }
}

// ======================= K1: message MLP, 4 warps, 64x64 warp tiles ===============
// 128 edges/block, 128 threads. Warp grid 2x2: wm = wid>>1, wn = wid&1.
// Warp tile 64(M) x 64(N); acc[4][8] (mt 16-row steps, nt 8-col steps).
__device__ __forceinline__ void msg_stage(
    int kc, float* abuf, float* wbuf,
    const int* sN, int nE, int e0,
    const float* ef, const float* ts,
    const float* tw, const float* tb, int tid)
{
    if (kc < 8) {
        const int* nodes = (kc < 4) ? sN : sN + 128;
        int q0 = (kc & 3) * 8;
        #pragma unroll
        for (int it = 0; it < 8; it++) {
            int idx = tid + 128 * it;
            int e = idx >> 3, q = idx & 7;
            cpa16(abuf + e * 36 + q * 4,
                  (const float4*)(g_memr + (size_t)nodes[e] * 128) + q0 + q, e < nE);
        }
    } else if (kc == 8) {
        #pragma unroll
        for (int it = 0; it < 8; it++) {
            int idx = tid + 128 * it;
            int e = idx >> 3, q = idx & 7;
            float4 v = make_float4(0.f, 0.f, 0.f, 0.f);
            if (e < nE) v = __ldg((const float4*)(ef + (size_t)(e0 + e) * 32) + q);
            *((float4*)(abuf + e * 36 + q * 4)) = to_tf32_4(v);
        }
    } else {
        for (int it = 0; it < 32; it++) {
            int idx = tid + 128 * it;
            int e = idx >> 5, c = idx & 31;
            float t = 0.f;
            if (e < nE) t = cosf(ts[e0 + e] * __ldg(tw + c) + __ldg(tb + c));
            abuf[e * 36 + c] = to_tf32(t);
        }
    }
    const float4* wsrc = (const float4*)(g_W1r + (size_t)kc * 32 * 128);
    #pragma unroll
    for (int it = 0; it < 8; it++) {
        int idx = tid + 128 * it;
        int r = idx >> 5, c = idx & 31;
        cpa16(wbuf + r * 136 + c * 4, wsrc + idx, true);
    }
}
__device__ __forceinline__ void msg_stage_w2(int kc, float* wbuf, int tid) {
    const float4* wsrc = (const float4*)(g_W2r + (size_t)kc * 32 * 128);
    #pragma unroll
    for (int it = 0; it < 8; it++) {
        int idx = tid + 128 * it;
        int r = idx >> 5, c = idx & 31;
        cpa16(wbuf + r * 136 + c * 4, wsrc + idx, true);
    }
}

__global__ __launch_bounds__(128, 2) void k_msg(
    const int* __restrict__ src, const int* __restrict__ dst,
    const float* __restrict__ ef, const float* __restrict__ ts,
    const float* __restrict__ tw, const float* __restrict__ tb,
    const float* __restrict__ b1, const float* __restrict__ b2,
    int E)
{
    float* sU  = smem;                 // 16896 (H stride 132)
    float* sA0 = smem;                 // 128*36
    float* sA1 = smem + 4608;          // 128*36
    float* sWa = smem + 16896;         // 32*136
    float* sWb = sWa + 4352;           // 32*136
    int*   sN  = (int*)(sWb + 4352);

    const int tid  = threadIdx.x;
    const int lane = tid & 31;
    const int wid  = tid >> 5;          // 0..3
    const int wm   = wid >> 1;          // 0..1
    const int wn   = wid & 1;           // 0..1
    const int grp  = lane >> 2;
    const int thr  = lane & 3;
    const int e0 = blockIdx.x * 128;
    const int nE = min(128, E - e0);

    sN[tid]       = (tid < nE) ? src[e0 + tid] : 0;
    sN[128 + tid] = (tid < nE) ? dst[e0 + tid] : 0;
    __syncthreads();

    float4 acc[4][8];
    #pragma unroll
    for (int mt = 0; mt < 4; mt++)
        #pragma unroll
        for (int nt = 0; nt < 8; nt++) acc[mt][nt] = make_float4(0.f, 0.f, 0.f, 0.f);

    msg_stage(0, sA0, sWa, sN, nE, e0, ef, ts, tw, tb, tid);
    CP_COMMIT();
    CP_WAIT(0);
    __syncthreads();

    // -------- GEMM1: K=320, 10 chunks, depth-1 prefetch --------
    #pragma unroll 1
    for (int kc = 0; kc < 10; kc++) {
        float* abuf = (kc & 1) ? sA1 : sA0;
        float* wbuf = (kc & 1) ? sWb : sWa;
        if (kc < 9) {
            msg_stage(kc + 1, (kc & 1) ? sA0 : sA1, (kc & 1) ? sWa : sWb,
                      sN, nE, e0, ef, ts, tw, tb, tid);
            CP_COMMIT();
        }
        #pragma unroll
        for (int ks = 0; ks < 4; ks++) {
            unsigned int a[4][4], b[8][2];
            #pragma unroll
            for (int mt = 0; mt < 4; mt++) {
                int r0 = (wm * 64 + mt * 16 + grp) * 36 + ks * 8 + thr;
                int r1 = r0 + 8 * 36;
                a[mt][0] = __float_as_uint(abuf[r0]);
                a[mt][1] = __float_as_uint(abuf[r1]);
                a[mt][2] = __float_as_uint(abuf[r0 + 4]);
                a[mt][3] = __float_as_uint(abuf[r1 + 4]);
            }
            #pragma unroll
            for (int nt = 0; nt < 8; nt++) {
                int col = wn * 64 + nt * 8 + grp;
                b[nt][0] = __float_as_uint(wbuf[(ks * 8 + thr) * 136 + col]);
                b[nt][1] = __float_as_uint(wbuf[(ks * 8 + thr + 4) * 136 + col]);
            }
            #pragma unroll
            for (int mt = 0; mt < 4; mt++)
                #pragma unroll
                for (int nt = 0; nt < 8; nt++)
                    mma_tf32(acc[mt][nt], a[mt], b[nt]);
        }
        if (kc < 9) {
            CP_WAIT(0);
            __syncthreads();
        }
    }
    __syncthreads();   // all GEMM1 reads done; sU can be overwritten by H

    msg_stage_w2(0, sWa, tid);
    CP_COMMIT();
    {
        #pragma unroll
        for (int mt = 0; mt < 4; mt++) {
            int r0 = wm * 64 + mt * 16 + grp;
            #pragma unroll
            for (int nt = 0; nt < 8; nt++) {
                int col = wn * 64 + nt * 8 + 2 * thr;
                float bc0 = __ldg(b1 + col), bc1 = __ldg(b1 + col + 1);
                sU[r0 * 132 + col]           = to_tf32(fmaxf(acc[mt][nt].x + bc0, 0.f));
                sU[r0 * 132 + col + 1]       = to_tf32(fmaxf(acc[mt][nt].y + bc1, 0.f));
                sU[(r0 + 8) * 132 + col]     = to_tf32(fmaxf(acc[mt][nt].z + bc0, 0.f));
                sU[(r0 + 8) * 132 + col + 1] = to_tf32(fmaxf(acc[mt][nt].w + bc1, 0.f));
                acc[mt][nt] = make_float4(0.f, 0.f, 0.f, 0.f);
            }
        }
    }
    CP_WAIT(0);
    __syncthreads();   // H + W2 chunk0 ready

    // -------- GEMM2: K=128, 4 chunks, depth-1 prefetch --------
    #pragma unroll 1
    for (int kc = 0; kc < 4; kc++) {
        float* wbuf = (kc & 1) ? sWb : sWa;
        if (kc < 3) {
            msg_stage_w2(kc + 1, (kc & 1) ? sWa : sWb, tid);
            CP_COMMIT();
        }
        #pragma unroll
        for (int ks = 0; ks < 4; ks++) {
            unsigned int a[4][4], b[8][2];
            int kbase = kc * 32 + ks * 8;
            #pragma unroll
            for (int mt = 0; mt < 4; mt++) {
                int r0 = (wm * 64 + mt * 16 + grp) * 132 + kbase + thr;
                int r1 = r0 + 8 * 132;
                a[mt][0] = __float_as_uint(sU[r0]);
                a[mt][1] = __float_as_uint(sU[r1]);
                a[mt][2] = __float_as_uint(sU[r0 + 4]);
                a[mt][3] = __float_as_uint(sU[r1 + 4]);
            }
            #pragma unroll
            for (int nt = 0; nt < 8; nt++) {
                int col = wn * 64 + nt * 8 + grp;
                b[nt][0] = __float_as_uint(wbuf[(ks * 8 + thr) * 136 + col]);
                b[nt][1] = __float_as_uint(wbuf[(ks * 8 + thr + 4) * 136 + col]);
            }
            #pragma unroll
            for (int mt = 0; mt < 4; mt++)
                #pragma unroll
                for (int nt = 0; nt < 8; nt++)
                    mma_tf32(acc[mt][nt], a[mt], b[nt]);
        }
        if (kc < 3) {
            CP_WAIT(0);
            __syncthreads();
        }
    }
    __syncthreads();   // GEMM2 reads of sU done before msg overwrite

    // -------- msg (+b2) -> sU, then float4 scatter --------
    {
        #pragma unroll
        for (int mt = 0; mt < 4; mt++) {
            int r0 = wm * 64 + mt * 16 + grp;
            #pragma unroll
            for (int nt = 0; nt < 8; nt++) {
                int col = wn * 64 + nt * 8 + 2 * thr;
                float bc0 = __ldg(b2 + col), bc1 = __ldg(b2 + col + 1);
                sU[r0 * 132 + col]           = acc[mt][nt].x + bc0;
                sU[r0 * 132 + col + 1]       = acc[mt][nt].y + bc1;
                sU[(r0 + 8) * 132 + col]     = acc[mt][nt].z + bc0;
                sU[(r0 + 8) * 132 + col + 1] = acc[mt][nt].w + bc1;
            }
        }
    }
    __syncthreads();

    if (tid < nE) {
        int ns = sN[tid], nd = sN[128 + tid];
        #pragma unroll 4
        for (int j4 = 0; j4 < 32; j4++) {
            float4 v = ((const float4*)(sU + tid * 132))[j4];
            atomicAdd((float4*)(g_aggr + (size_t)ns * 128) + j4, v);
            atomicAdd((float4*)(g_aggr + (size_t)nd * 128) + j4, v);
        }
        atomicAdd(&g_cnt[ns], 1.f);
        atomicAdd(&g_cnt[nd], 1.f);
    }
}

// ======================= K2: GRU via tf32 MMA, double-buffered (R11) ==============
__device__ __forceinline__ void gru_stage(
    int kc, int sweep, float* abuf, float* wbuf,
    const float* sCnt, int n0, int nN, int tid)
{
    #pragma unroll
    for (int it = 0; it < 2; it++) {
        int idx = tid + 256 * it;
        int e = idx >> 3, q = idx & 7;
        if (kc < 4) {
            float4 v = make_float4(0.f, 0.f, 0.f, 0.f);
            if (e < nN) {
                v = *((const float4*)(g_aggr + (size_t)(n0 + e) * 128) + kc * 8 + q);
                float cnt = sCnt[e];
                float inv = (cnt > 0.f) ? (1.f / cnt) : 0.f;
                v.x *= inv; v.y *= inv; v.z *= inv; v.w *= inv;
            }
            *((float4*)(abuf + e * 36 + q * 4)) = to_tf32_4(v);
        } else {
            cpa16(abuf + e * 36 + q * 4,
                  (const float4*)(g_memr + (size_t)(n0 + e) * 128) + (kc - 4) * 8 + q,
                  e < nN);
        }
    }
    const float* wsrc = g_Wg + (size_t)kc * 32 * 512 + sweep * 256;
    #pragma unroll
    for (int it = 0; it < 8; it++) {
        int idx = tid + 256 * it;
        int r = idx >> 6, c = idx & 63;
        cpa16(wbuf + r * 264 + c * 4, (const float4*)(wsrc + (size_t)r * 512) + c, true);
    }
}

__global__ __launch_bounds__(256, 2) void k_gru(
    const float* __restrict__ memory,
    const float* __restrict__ bih, const float* __restrict__ bhh)
{
    float* sA0  = smem;
    float* sA1  = smem + 2304;
    float* sW0  = smem + 4608;
    float* sW1  = smem + 13056;
    float* sCnt = smem + 21504;

    const int tid  = threadIdx.x;
    const int lane = tid & 31;
    const int wid  = tid >> 5;
    const int grp  = lane >> 2;
    const int thr  = lane & 3;
    const int n0 = blockIdx.x * 64;
    const int nN = min(64, N_NODES - n0);

    if (tid < 64) sCnt[tid] = (tid < nN) ? g_cnt[n0 + tid] : 0.f;
    __syncthreads();

    #pragma unroll 1
    for (int sweep = 0; sweep < 2; sweep++) {
        float4 acc[4][4];
        #pragma unroll
        for (int mt = 0; mt < 4; mt++)
            #pragma unroll
            for (int nt = 0; nt < 4; nt++) acc[mt][nt] = make_float4(0.f, 0.f, 0.f, 0.f);

        gru_stage(0, sweep, sA0, sW0, sCnt, n0, nN, tid);
        CP_COMMIT();
        CP_WAIT(0);
        __syncthreads();

        #pragma unroll 1
        for (int kc = 0; kc < 8; kc++) {
            float* abuf = (kc & 1) ? sA1 : sA0;
            float* wbuf = (kc & 1) ? sW1 : sW0;
            if (kc < 7) {
                gru_stage(kc + 1, sweep, (kc & 1) ? sA0 : sA1, (kc & 1) ? sW0 : sW1,
                          sCnt, n0, nN, tid);
                CP_COMMIT();
            }
            #pragma unroll
            for (int ks = 0; ks < 4; ks++) {
                unsigned int a[4][4], b[4][2];
                #pragma unroll
                for (int mt = 0; mt < 4; mt++) {
                    int r0 = (mt * 16 + grp) * 36 + ks * 8 + thr;
                    int r1 = r0 + 8 * 36;
                    a[mt][0] = __float_as_uint(abuf[r0]);
                    a[mt][1] = __float_as_uint(abuf[r1]);
                    a[mt][2] = __float_as_uint(abuf[r0 + 4]);
                    a[mt][3] = __float_as_uint(abuf[r1 + 4]);
                }
                #pragma unroll
                for (int nt = 0; nt < 4; nt++) {
                    int col = wid * 32 + nt * 8 + grp;
                    b[nt][0] = __float_as_uint(wbuf[(ks * 8 + thr) * 264 + col]);
                    b[nt][1] = __float_as_uint(wbuf[(ks * 8 + thr + 4) * 264 + col]);
                }
                #pragma unroll
                for (int mt = 0; mt < 4; mt++)
                    #pragma unroll
                    for (int nt = 0; nt < 4; nt++)
                        mma_tf32(acc[mt][nt], a[mt], b[nt]);
            }
            if (kc < 7) {
                CP_WAIT(0);
                __syncthreads();
            }
        }
        __syncthreads();

        int j0 = sweep * 64 + wid * 8 + 2 * thr;
        float br0 = __ldg(bih + j0) + __ldg(bhh + j0);
        float br1 = __ldg(bih + j0 + 1) + __ldg(bhh + j0 + 1);
        float bz0 = __ldg(bih + 128 + j0) + __ldg(bhh + 128 + j0);
        float bz1 = __ldg(bih + 128 + j0 + 1) + __ldg(bhh + 128 + j0 + 1);
        float bi0 = __ldg(bih + 256 + j0),      bi1 = __ldg(bih + 256 + j0 + 1);
        float bh0 = __ldg(bhh + 256 + j0),      bh1 = __ldg(bhh + 256 + j0 + 1);

        #pragma unroll
        for (int mt = 0; mt < 4; mt++) {
            #pragma unroll
            for (int half = 0; half < 2; half++) {
                int row = mt * 16 + grp + half * 8;
                if (row < nN) {
                    float rp0 = half ? acc[mt][0].z : acc[mt][0].x;
                    float rp1 = half ? acc[mt][0].w : acc[mt][0].y;
                    float zp0 = half ? acc[mt][1].z : acc[mt][1].x;
                    float zp1 = half ? acc[mt][1].w : acc[mt][1].y;
                    float ip0 = half ? acc[mt][2].z : acc[mt][2].x;
                    float ip1 = half ? acc[mt][2].w : acc[mt][2].y;
                    float hp0 = half ? acc[mt][3].z : acc[mt][3].x;
                    float hp1 = half ? acc[mt][3].w : acc[mt][3].y;

                    float2 hv = *(const float2*)(memory + (size_t)(n0 + row) * 128 + j0);
                    float cnt = sCnt[row];

                    float r0g = sigm(rp0 + br0), r1g = sigm(rp1 + br1);
                    float z0g = sigm(zp0 + bz0), z1g = sigm(zp1 + bz1);
                    float n0g = tanhf(ip0 + bi0 + r0g * (hp0 + bh0));
                    float n1g = tanhf(ip1 + bi1 + r1g * (hp1 + bh1));
                    float2 res;
                    res.x = (cnt > 0.f) ? to_tf32((1.f - z0g) * n0g + z0g * hv.x) : to_tf32(hv.x);
                    res.y = (cnt > 0.f) ? to_tf32((1.f - z1g) * n1g + z1g * hv.y) : to_tf32(hv.y);
                    *(float2*)(g_newmem + (size_t)(n0 + row) * 128 + j0) = res;
                }
            }
        }
    }
}

// ======================= K3: embeddings (R11) ====================================
__device__ __forceinline__ void emb_stage(
    int kc, float* abuf, float* wbuf,
    const int* sN, int nE, int e0, const float* feats, int tid)
{
    if (kc < 4) {
        int q0 = kc * 8;
        #pragma unroll
        for (int it = 0; it < 4; it++) {
            int idx = tid + 256 * it;
            int e = idx >> 3, q = idx & 7;
            cpa16(abuf + e * 36 + q * 4,
                  (const float4*)(g_newmem + (size_t)sN[e] * 128) + q0 + q, e < nE);
        }
    } else {
        int fc = kc - 4;
        #pragma unroll
        for (int it = 0; it < 4; it++) {
            int idx = tid + 256 * it;
            int e = idx >> 3, q = idx & 7;
            float4 v = make_float4(0.f, 0.f, 0.f, 0.f);
            if (e < nE) v = __ldg((const float4*)(feats + (size_t)(e0 + e) * 64) + fc * 8 + q);
            *((float4*)(abuf + e * 36 + q * 4)) = to_tf32_4(v);
        }
    }
    const float4* wsrc = (const float4*)(g_eW1r + (size_t)kc * 32 * 64);
    #pragma unroll
    for (int it = 0; it < 2; it++) {
        int idx = tid + 256 * it;
        int r = idx >> 4, c = idx & 15;
        cpa16(wbuf + r * 72 + c * 4, wsrc + idx, true);
    }
}

__global__ __launch_bounds__(256, 2) void k_emb(
    const int* __restrict__ src, const int* __restrict__ dst,
    const float* __restrict__ sf, const float* __restrict__ df,
    const float* __restrict__ b1,
    float* __restrict__ out, int E)
{
    float* sA0 = smem;
    float* sW0 = smem + 4608;
    float* sHs = smem + 6912;
    float* sHd = smem + 15616;
    float* sA1 = smem + 15616;
    float* sW1 = smem + 20224;
    float* sM  = smem;
    float* sv  = smem + 4096;
    int*   sN  = (int*)(smem + 24320);

    const int tid  = threadIdx.x;
    const int lane = tid & 31;
    const int wid  = tid >> 5;
    const int wm   = wid >> 1;
    const int wn   = wid & 1;
    const int grp  = lane >> 2;
    const int thr  = lane & 3;
    const int e0 = blockIdx.x * 128;
    const int nE = min(128, E - e0);

    #pragma unroll 1
    for (int side = 0; side < 2; side++) {
        const int* nodes = side ? dst : src;
        const float* feats = side ? df : sf;
        float* sH = side ? sHd : sHs;

        __syncthreads();
        if (tid < 128) sN[tid] = (tid < nE) ? nodes[e0 + tid] : 0;
        __syncthreads();

        float4 acc[2][4];
        #pragma unroll
        for (int mt = 0; mt < 2; mt++)
            #pragma unroll
            for (int nt = 0; nt < 4; nt++) acc[mt][nt] = make_float4(0.f, 0.f, 0.f, 0.f);

        emb_stage(0, sA0, sW0, sN, nE, e0, feats, tid);
        CP_COMMIT();
        CP_WAIT(0);
        __syncthreads();

        #pragma unroll 1
        for (int kc = 0; kc < 6; kc++) {
            float* abuf = (kc & 1) ? sA1 : sA0;
            float* wbuf = (kc & 1) ? sW1 : sW0;
            if (kc < 5) {
                emb_stage(kc + 1, (kc & 1) ? sA0 : sA1, (kc & 1) ? sW0 : sW1,
                          sN, nE, e0, feats, tid);
                CP_COMMIT();
            }
            #pragma unroll
            for (int ks = 0; ks < 4; ks++) {
                unsigned int a[2][4], b[4][2];
                #pragma unroll
                for (int mt = 0; mt < 2; mt++) {
                    int r0 = (wm * 32 + mt * 16 + grp) * 36 + ks * 8 + thr;
                    int r1 = r0 + 8 * 36;
                    a[mt][0] = __float_as_uint(abuf[r0]);
                    a[mt][1] = __float_as_uint(abuf[r1]);
                    a[mt][2] = __float_as_uint(abuf[r0 + 4]);
                    a[mt][3] = __float_as_uint(abuf[r1 + 4]);
                }
                #pragma unroll
                for (int nt = 0; nt < 4; nt++) {
                    int col = wn * 32 + nt * 8 + grp;
                    b[nt][0] = __float_as_uint(wbuf[(ks * 8 + thr) * 72 + col]);
                    b[nt][1] = __float_as_uint(wbuf[(ks * 8 + thr + 4) * 72 + col]);
                }
                #pragma unroll
                for (int mt = 0; mt < 2; mt++)
                    #pragma unroll
                    for (int nt = 0; nt < 4; nt++)
                        mma_tf32(acc[mt][nt], a[mt], b[nt]);
            }
            if (kc < 5) {
                CP_WAIT(0);
                __syncthreads();
            }
        }
        __syncthreads();

        {
            float bc0[4], bc1[4];
            #pragma unroll
            for (int nt = 0; nt < 4; nt++) {
                int col = wn * 32 + nt * 8 + 2 * thr;
                bc0[nt] = __ldg(b1 + col);
                bc1[nt] = __ldg(b1 + col + 1);
            }
            #pragma unroll
            for (int mt = 0; mt < 2; mt++) {
                int r0 = wm * 32 + mt * 16 + grp;
                #pragma unroll
                for (int nt = 0; nt < 4; nt++) {
                    int col = wn * 32 + nt * 8 + 2 * thr;
                    sH[r0 * 68 + col]           = fmaxf(acc[mt][nt].x + bc0[nt], 0.f);
                    sH[r0 * 68 + col + 1]       = fmaxf(acc[mt][nt].y + bc1[nt], 0.f);
                    sH[(r0 + 8) * 68 + col]     = fmaxf(acc[mt][nt].z + bc0[nt], 0.f);
                    sH[(r0 + 8) * 68 + col + 1] = fmaxf(acc[mt][nt].w + bc1[nt], 0.f);
                }
            }
        }
    }
    __syncthreads();

    #pragma unroll
    for (int it = 0; it < 4; it++)
        ((float4*)sM)[tid + 256 * it] = ((const float4*)g_M)[tid + 256 * it];
    if (tid < 16) ((float4*)sv)[tid] = ((const float4*)g_v)[tid];
    __syncthreads();

    const int tx = tid & 15, ty = tid >> 4;
    float4 t[8];
    #pragma unroll
    for (int i = 0; i < 8; i++) t[i] = make_float4(0.f, 0.f, 0.f, 0.f);
    #pragma unroll 8
    for (int kk = 0; kk < 64; kk++) {
        float4 m = ((const float4*)sM)[kk * 16 + tx];
        #pragma unroll
        for (int i = 0; i < 8; i++) {
            float a = sHd[(i * 16 + ty) * 68 + kk];
            t[i].x = fmaf(a, m.x, t[i].x);
            t[i].y = fmaf(a, m.y, t[i].y);
            t[i].z = fmaf(a, m.z, t[i].z);
            t[i].w = fmaf(a, m.w, t[i].w);
        }
    }

    float c0 = g_c0;
    float4 vv = ((const float4*)sv)[tx];
    float p[8];
    #pragma unroll
    for (int i = 0; i < 8; i++) {
        int row = i * 16 + ty;
        float4 hs = ((const float4*)(sHs + row * 68))[tx];
        float4 hd = ((const float4*)(sHd + row * 68))[tx];
        p[i] = hs.x * t[i].x + hs.y * t[i].y + hs.z * t[i].z + hs.w * t[i].w
             + (hs.x + hd.x) * vv.x + (hs.y + hd.y) * vv.y
             + (hs.z + hd.z) * vv.z + (hs.w + hd.w) * vv.w;
    }
    #pragma unroll
    for (int m = 1; m < 16; m <<= 1)
        #pragma unroll
        for (int i = 0; i < 8; i++)
            p[i] += __shfl_xor_sync(0xffffffffu, p[i], m);
    if (tx == 0) {
        #pragma unroll
        for (int i = 0; i < 8; i++) {
            int e = i * 16 + ty;
            if (e < nE) out[e0 + e] = p[i] + c0;
        }
    }
}

// ---------------- host launch ----------------
extern "C" void kernel_launch(void* const* d_in, const int* in_sizes, int n_in,
                              void* d_out, int out_size)
{
    const int*   src   = (const int*)d_in[0];
    const int*   dst   = (const int*)d_in[1];
    const float* ef    = (const float*)d_in[2];
    const float* ts    = (const float*)d_in[3];
    const float* sf    = (const float*)d_in[4];
    const float* df    = (const float*)d_in[5];
    const float* mem   = (const float*)d_in[6];
    const float* tw    = (const float*)d_in[7];
    const float* tb    = (const float*)d_in[8];
    const float* mw1   = (const float*)d_in[9];
    const float* mb1   = (const float*)d_in[10];
    const float* mw2   = (const float*)d_in[11];
    const float* mb2   = (const float*)d_in[12];
    const float* gwih  = (const float*)d_in[13];
    const float* gwhh  = (const float*)d_in[14];
    const float* gbih  = (const float*)d_in[15];
    const float* gbhh  = (const float*)d_in[16];
    const float* ew1   = (const float*)d_in[17];
    const float* eb1   = (const float*)d_in[18];
    const float* ew2   = (const float*)d_in[19];
    const float* eb2   = (const float*)d_in[20];
    float* out = (float*)d_out;

    const int E = in_sizes[0];

    const int SMEM1 = (16896 + 2 * 4352) * 4 + 256 * 4;
    const int SMEM2 = (2 * 2304 + 2 * 8448 + 64) * 4;
    const int SMEM3 = 24320 * 4 + 128 * 4;

    cudaFuncSetAttribute(k_msg, cudaFuncAttributeMaxDynamicSharedMemorySize, SMEM1);
    cudaFuncSetAttribute(k_gru, cudaFuncAttributeMaxDynamicSharedMemorySize, SMEM2);
    cudaFuncSetAttribute(k_emb, cudaFuncAttributeMaxDynamicSharedMemorySize, SMEM3);

    k_prep<<<2048, 256>>>(mem, mw1, mw2, ew1, gwih, gwhh);
    k_pre<<<1, 256>>>(ew2, eb2);
    k_msg<<<(E + 127) / 128, 128, SMEM1>>>(src, dst, ef, ts, tw, tb, mb1, mb2, E);
    k_gru<<<(N_NODES + 63) / 64, 256, SMEM2>>>(mem, gbih, gbhh);
    k_emb<<<(E + 127) / 128, 256, SMEM3>>>(src, dst, sf, df, eb1, out, E);
}

// round 14
// speedup vs baseline: 1.0907x; 1.0907x over previous
#include <cuda_runtime.h>
#include <stdint.h>
#include <math.h>

#define N_NODES 100000
#define MEM_DIM 128
#define MSG_DIM 128

// ---------------- scratch (static device globals; no allocation) ----------------
__device__ float g_aggr[(size_t)N_NODES * MSG_DIM];
__device__ float g_cnt[N_NODES];
__device__ float g_newmem[(size_t)N_NODES * MEM_DIM]; // tf32-rounded at write
__device__ float g_memr[(size_t)N_NODES * MEM_DIM];   // tf32-rounded memory
__device__ float g_M[64 * 64];
__device__ float g_v[64];
__device__ float g_c0;
__device__ float g_Wg[256 * 512];  // gate-interleaved GRU weights (tf32)
__device__ float g_W1r[320 * 128]; // msg W1 tf32
__device__ float g_W2r[128 * 128]; // msg W2 tf32
__device__ float g_eW1r[192 * 64]; // emb W1 tf32

extern __shared__ float smem[];

// ---------------- helpers ----------------
__device__ __forceinline__ float to_tf32(float x) {
    unsigned int u;
    asm("cvt.rna.tf32.f32 %0, %1;" : "=r"(u) : "f"(x));
    return __uint_as_float(u);
}
__device__ __forceinline__ float4 to_tf32_4(float4 v) {
    v.x = to_tf32(v.x); v.y = to_tf32(v.y);
    v.z = to_tf32(v.z); v.w = to_tf32(v.w);
    return v;
}
__device__ __forceinline__ void mma_tf32(float4& c, const unsigned int a[4], const unsigned int b[2]) {
    asm volatile(
        "mma.sync.aligned.m16n8k8.row.col.f32.tf32.tf32.f32 "
        "{%0,%1,%2,%3},{%4,%5,%6,%7},{%8,%9},{%0,%1,%2,%3};\n"
        : "+f"(c.x), "+f"(c.y), "+f"(c.z), "+f"(c.w)
        : "r"(a[0]), "r"(a[1]), "r"(a[2]), "r"(a[3]), "r"(b[0]), "r"(b[1]));
}
__device__ __forceinline__ float sigm(float x) { return 1.f / (1.f + expf(-x)); }

__device__ __forceinline__ void cpa16(float* dst, const void* src, bool pred) {
    unsigned sa = (unsigned)__cvta_generic_to_shared(dst);
    asm volatile("cp.async.ca.shared.global [%0], [%1], 16, %2;\n"
                 :: "r"(sa), "l"(src), "r"(pred ? 16 : 0));
}
#define CP_COMMIT() asm volatile("cp.async.commit_group;\n" ::: "memory")
#define CP_WAIT(n)  asm volatile("cp.async.wait_group %0;\n" :: "n"(n) : "memory")

// ---------------- K-prep: zero + tf32 pre-round + GRU weight build ----------------
__global__ void k_prep(const float* __restrict__ memory,
                       const float* __restrict__ W1, const float* __restrict__ W2,
                       const float* __restrict__ eW1,
                       const float* __restrict__ Wih, const float* __restrict__ Whh) {
    size_t stride = (size_t)gridDim.x * blockDim.x;
    size_t t = (size_t)blockIdx.x * blockDim.x + threadIdx.x;
    float4 z = make_float4(0.f, 0.f, 0.f, 0.f);
    for (size_t i = t; i < (size_t)N_NODES * MSG_DIM / 4; i += stride) ((float4*)g_aggr)[i] = z;
    for (size_t i = t; i < N_NODES; i += stride) g_cnt[i] = 0.f;
    for (size_t i = t; i < (size_t)N_NODES * MEM_DIM / 4; i += stride)
        ((float4*)g_memr)[i] = to_tf32_4(__ldg((const float4*)memory + i));
    for (size_t i = t; i < 320 * 128 / 4; i += stride)
        ((float4*)g_W1r)[i] = to_tf32_4(__ldg((const float4*)W1 + i));
    for (size_t i = t; i < 128 * 128 / 4; i += stride)
        ((float4*)g_W2r)[i] = to_tf32_4(__ldg((const float4*)W2 + i));
    for (size_t i = t; i < 192 * 64 / 4; i += stride)
        ((float4*)g_eW1r)[i] = to_tf32_4(__ldg((const float4*)eW1 + i));
    for (size_t p = t; p < 256 * 512; p += stride) {
        int k = (int)(p >> 9), c = (int)(p & 511);
        int jb = c >> 5, tt = c & 31, q = tt >> 3;
        int j = jb * 8 + (tt & 7);
        float w;
        if (q == 0)      w = (k < 128) ? Wih[(size_t)j * 128 + k]
                                       : Whh[(size_t)j * 128 + (k - 128)];
        else if (q == 1) w = (k < 128) ? Wih[(size_t)(128 + j) * 128 + k]
                                       : Whh[(size_t)(128 + j) * 128 + (k - 128)];
        else if (q == 2) w = (k < 128) ? Wih[(size_t)(256 + j) * 128 + k] : 0.f;
        else             w = (k < 128) ? 0.f : Whh[(size_t)(256 + j) * 128 + (k - 128)];
        g_Wg[p] = to_tf32(w);
    }
}

// ---------------- K-pre: bilinear precompute for emb ----------------
__global__ void k_pre(const float* __restrict__ W2, const float* __restrict__ b2) {
    __shared__ float sW2[64 * 64];
    __shared__ float sb2[64];
    int tid = threadIdx.x;
    for (int i = tid; i < 64 * 64; i += 256) sW2[i] = W2[i];
    if (tid < 64) sb2[tid] = b2[tid];
    __syncthreads();
    for (int p = tid; p < 64 * 64; p += 256) {
        int j = p >> 6, k = p & 63;
        float s = 0.f;
        #pragma unroll 16
        for (int c = 0; c < 64; c++) s = fmaf(sW2[j * 64 + c], sW2[k * 64 + c], s);
        g_M[p] = s;
    }
    if (tid < 64) {
        float s = 0.f;
        #pragma unroll 16
        for (int c = 0; c < 64; c++) s = fmaf(sW2[tid * 64 + c], sb2[c], s);
        g_v[tid] = s;
    }
    if (tid == 0) {
        float s = 0.f;
        for (int c = 0; c < 64; c++) s = fmaf(sb2[c], sb2[c], s);
        g_c0 = s;
    }
}

// ======================= K1: message MLP (R11: 256 threads, 2x4 warps) ============
__device__ __forceinline__ void msg_stage(
    int kc, float* abuf, float* wbuf,
    const int* sN, int nE, int e0,
    const float* ef, const float* ts,
    const float* tw, const float* tb, int tid)
{
    if (kc < 8) {
        const int* nodes = (kc < 4) ? sN : sN + 128;
        int q0 = (kc & 3) * 8;
        #pragma unroll
        for (int it = 0; it < 4; it++) {
            int idx = tid + 256 * it;
            int e = idx >> 3, q = idx & 7;
            cpa16(abuf + e * 36 + q * 4,
                  (const float4*)(g_memr + (size_t)nodes[e] * 128) + q0 + q, e < nE);
        }
    } else if (kc == 8) {
        #pragma unroll
        for (int it = 0; it < 4; it++) {
            int idx = tid + 256 * it;
            int e = idx >> 3, q = idx & 7;
            float4 v = make_float4(0.f, 0.f, 0.f, 0.f);
            if (e < nE) v = __ldg((const float4*)(ef + (size_t)(e0 + e) * 32) + q);
            *((float4*)(abuf + e * 36 + q * 4)) = to_tf32_4(v);
        }
    } else {
        for (int it = 0; it < 16; it++) {
            int idx = tid + 256 * it;
            int e = idx >> 5, c = idx & 31;
            float t = 0.f;
            if (e < nE) t = cosf(ts[e0 + e] * __ldg(tw + c) + __ldg(tb + c));
            abuf[e * 36 + c] = to_tf32(t);
        }
    }
    const float4* wsrc = (const float4*)(g_W1r + (size_t)kc * 32 * 128);
    #pragma unroll
    for (int it = 0; it < 4; it++) {
        int idx = tid + 256 * it;
        int r = idx >> 5, c = idx & 31;
        cpa16(wbuf + r * 136 + c * 4, wsrc + idx, true);
    }
}
__device__ __forceinline__ void msg_stage_w2(int kc, float* wbuf, int tid) {
    const float4* wsrc = (const float4*)(g_W2r + (size_t)kc * 32 * 128);
    #pragma unroll
    for (int it = 0; it < 4; it++) {
        int idx = tid + 256 * it;
        int r = idx >> 5, c = idx & 31;
        cpa16(wbuf + r * 136 + c * 4, wsrc + idx, true);
    }
}

__global__ __launch_bounds__(256, 2) void k_msg(
    const int* __restrict__ src, const int* __restrict__ dst,
    const float* __restrict__ ef, const float* __restrict__ ts,
    const float* __restrict__ tw, const float* __restrict__ tb,
    const float* __restrict__ b1, const float* __restrict__ b2,
    int E)
{
    float* sU  = smem;
    float* sA0 = smem;
    float* sA1 = smem + 4608;
    float* sWa = smem + 16896;
    float* sWb = sWa + 4352;
    int*   sN  = (int*)(sWb + 4352);

    const int tid  = threadIdx.x;
    const int lane = tid & 31;
    const int wid  = tid >> 5;
    const int wm   = wid >> 2;
    const int wn   = wid & 3;
    const int grp  = lane >> 2;
    const int thr  = lane & 3;
    const int e0 = blockIdx.x * 128;
    const int nE = min(128, E - e0);

    if (tid < 128) sN[tid] = (tid < nE) ? src[e0 + tid] : 0;
    else           sN[tid] = (tid - 128 < nE) ? dst[e0 + tid - 128] : 0;
    __syncthreads();

    float4 acc[4][4];
    #pragma unroll
    for (int mt = 0; mt < 4; mt++)
        #pragma unroll
        for (int nt = 0; nt < 4; nt++) acc[mt][nt] = make_float4(0.f, 0.f, 0.f, 0.f);

    msg_stage(0, sA0, sWa, sN, nE, e0, ef, ts, tw, tb, tid);
    CP_COMMIT();
    CP_WAIT(0);
    __syncthreads();

    #pragma unroll 1
    for (int kc = 0; kc < 10; kc++) {
        float* abuf = (kc & 1) ? sA1 : sA0;
        float* wbuf = (kc & 1) ? sWb : sWa;
        if (kc < 9) {
            msg_stage(kc + 1, (kc & 1) ? sA0 : sA1, (kc & 1) ? sWa : sWb,
                      sN, nE, e0, ef, ts, tw, tb, tid);
            CP_COMMIT();
        }
        #pragma unroll
        for (int ks = 0; ks < 4; ks++) {
            unsigned int a[4][4], b[4][2];
            #pragma unroll
            for (int mt = 0; mt < 4; mt++) {
                int r0 = (wm * 64 + mt * 16 + grp) * 36 + ks * 8 + thr;
                int r1 = r0 + 8 * 36;
                a[mt][0] = __float_as_uint(abuf[r0]);
                a[mt][1] = __float_as_uint(abuf[r1]);
                a[mt][2] = __float_as_uint(abuf[r0 + 4]);
                a[mt][3] = __float_as_uint(abuf[r1 + 4]);
            }
            #pragma unroll
            for (int nt = 0; nt < 4; nt++) {
                int col = wn * 32 + nt * 8 + grp;
                b[nt][0] = __float_as_uint(wbuf[(ks * 8 + thr) * 136 + col]);
                b[nt][1] = __float_as_uint(wbuf[(ks * 8 + thr + 4) * 136 + col]);
            }
            #pragma unroll
            for (int mt = 0; mt < 4; mt++)
                #pragma unroll
                for (int nt = 0; nt < 4; nt++)
                    mma_tf32(acc[mt][nt], a[mt], b[nt]);
        }
        if (kc < 9) {
            CP_WAIT(0);
            __syncthreads();
        }
    }
    __syncthreads();

    msg_stage_w2(0, sWa, tid);
    CP_COMMIT();
    {
        float bc0[4], bc1[4];
        #pragma unroll
        for (int nt = 0; nt < 4; nt++) {
            int col = wn * 32 + nt * 8 + 2 * thr;
            bc0[nt] = __ldg(b1 + col);
            bc1[nt] = __ldg(b1 + col + 1);
        }
        #pragma unroll
        for (int mt = 0; mt < 4; mt++) {
            int r0 = wm * 64 + mt * 16 + grp;
            #pragma unroll
            for (int nt = 0; nt < 4; nt++) {
                int col = wn * 32 + nt * 8 + 2 * thr;
                sU[r0 * 132 + col]           = to_tf32(fmaxf(acc[mt][nt].x + bc0[nt], 0.f));
                sU[r0 * 132 + col + 1]       = to_tf32(fmaxf(acc[mt][nt].y + bc1[nt], 0.f));
                sU[(r0 + 8) * 132 + col]     = to_tf32(fmaxf(acc[mt][nt].z + bc0[nt], 0.f));
                sU[(r0 + 8) * 132 + col + 1] = to_tf32(fmaxf(acc[mt][nt].w + bc1[nt], 0.f));
                acc[mt][nt] = make_float4(0.f, 0.f, 0.f, 0.f);
            }
        }
    }
    CP_WAIT(0);
    __syncthreads();

    #pragma unroll 1
    for (int kc = 0; kc < 4; kc++) {
        float* wbuf = (kc & 1) ? sWb : sWa;
        if (kc < 3) {
            msg_stage_w2(kc + 1, (kc & 1) ? sWa : sWb, tid);
            CP_COMMIT();
        }
        #pragma unroll
        for (int ks = 0; ks < 4; ks++) {
            unsigned int a[4][4], b[4][2];
            int kbase = kc * 32 + ks * 8;
            #pragma unroll
            for (int mt = 0; mt < 4; mt++) {
                int r0 = (wm * 64 + mt * 16 + grp) * 132 + kbase + thr;
                int r1 = r0 + 8 * 132;
                a[mt][0] = __float_as_uint(sU[r0]);
                a[mt][1] = __float_as_uint(sU[r1]);
                a[mt][2] = __float_as_uint(sU[r0 + 4]);
                a[mt][3] = __float_as_uint(sU[r1 + 4]);
            }
            #pragma unroll
            for (int nt = 0; nt < 4; nt++) {
                int col = wn * 32 + nt * 8 + grp;
                b[nt][0] = __float_as_uint(wbuf[(ks * 8 + thr) * 136 + col]);
                b[nt][1] = __float_as_uint(wbuf[(ks * 8 + thr + 4) * 136 + col]);
            }
            #pragma unroll
            for (int mt = 0; mt < 4; mt++)
                #pragma unroll
                for (int nt = 0; nt < 4; nt++)
                    mma_tf32(acc[mt][nt], a[mt], b[nt]);
        }
        if (kc < 3) {
            CP_WAIT(0);
            __syncthreads();
        }
    }
    __syncthreads();

    {
        float bc0[4], bc1[4];
        #pragma unroll
        for (int nt = 0; nt < 4; nt++) {
            int col = wn * 32 + nt * 8 + 2 * thr;
            bc0[nt] = __ldg(b2 + col);
            bc1[nt] = __ldg(b2 + col + 1);
        }
        #pragma unroll
        for (int mt = 0; mt < 4; mt++) {
            int r0 = wm * 64 + mt * 16 + grp;
            #pragma unroll
            for (int nt = 0; nt < 4; nt++) {
                int col = wn * 32 + nt * 8 + 2 * thr;
                sU[r0 * 132 + col]           = acc[mt][nt].x + bc0[nt];
                sU[r0 * 132 + col + 1]       = acc[mt][nt].y + bc1[nt];
                sU[(r0 + 8) * 132 + col]     = acc[mt][nt].z + bc0[nt];
                sU[(r0 + 8) * 132 + col + 1] = acc[mt][nt].w + bc1[nt];
            }
        }
    }
    __syncthreads();

    {
        const int tx = tid & 15, ty = tid >> 4;
        #pragma unroll
        for (int i = 0; i < 8; i++) {
            int e = i * 16 + ty;
            if (e < nE) {
                float4 v0 = ((const float4*)(sU + e * 132))[tx];
                float4 v1 = ((const float4*)(sU + e * 132))[16 + tx];
                int ns = sN[e], nd = sN[128 + e];
                atomicAdd((float4*)(g_aggr + (size_t)ns * 128) + tx, v0);
                atomicAdd((float4*)(g_aggr + (size_t)ns * 128) + 16 + tx, v1);
                atomicAdd((float4*)(g_aggr + (size_t)nd * 128) + tx, v0);
                atomicAdd((float4*)(g_aggr + (size_t)nd * 128) + 16 + tx, v1);
            }
        }
    }
    if (tid < nE) {
        atomicAdd(&g_cnt[sN[tid]], 1.f);
        atomicAdd(&g_cnt[sN[128 + tid]], 1.f);
    }
}

// ======================= K2: GRU, zero-pad MMAs skipped ===========================
__device__ __forceinline__ void gru_stage(
    int kc, int sweep, float* abuf, float* wbuf,
    const float* sCnt, int n0, int nN, int tid)
{
    #pragma unroll
    for (int it = 0; it < 2; it++) {
        int idx = tid + 256 * it;
        int e = idx >> 3, q = idx & 7;
        if (kc < 4) {
            float4 v = make_float4(0.f, 0.f, 0.f, 0.f);
            if (e < nN) {
                v = *((const float4*)(g_aggr + (size_t)(n0 + e) * 128) + kc * 8 + q);
                float cnt = sCnt[e];
                float inv = (cnt > 0.f) ? (1.f / cnt) : 0.f;
                v.x *= inv; v.y *= inv; v.z *= inv; v.w *= inv;
            }
            *((float4*)(abuf + e * 36 + q * 4)) = to_tf32_4(v);
        } else {
            cpa16(abuf + e * 36 + q * 4,
                  (const float4*)(g_memr + (size_t)(n0 + e) * 128) + (kc - 4) * 8 + q,
                  e < nN);
        }
    }
    // W staging: skip the all-zero gate blocks (zfill keeps them zero).
    // f4-block within each 32-col group: 0,1=r 2,3=z 4,5=i_n 6,7=h_n
    const float* wsrc = g_Wg + (size_t)kc * 32 * 512 + sweep * 256;
    #pragma unroll
    for (int it = 0; it < 8; it++) {
        int idx = tid + 256 * it;
        int r = idx >> 6, c = idx & 63;
        int blk = c & 7;
        bool nonzero = (kc < 4) ? (blk < 6) : !(blk == 4 || blk == 5);
        cpa16(wbuf + r * 264 + c * 4,
              (const float4*)(wsrc + (size_t)r * 512) + c, nonzero);
    }
}

// MMA over 3 active nt column-groups (compile-time when inlined with constants)
__device__ __forceinline__ void gru_mma3(
    const float* abuf, const float* wbuf, int grp, int thr, int wid,
    int nA, int nB, int nC, float4 acc[4][4])
{
    #pragma unroll
    for (int ks = 0; ks < 4; ks++) {
        unsigned int a[4][4];
        #pragma unroll
        for (int mt = 0; mt < 4; mt++) {
            int r0 = (mt * 16 + grp) * 36 + ks * 8 + thr;
            int r1 = r0 + 8 * 36;
            a[mt][0] = __float_as_uint(abuf[r0]);
            a[mt][1] = __float_as_uint(abuf[r1]);
            a[mt][2] = __float_as_uint(abuf[r0 + 4]);
            a[mt][3] = __float_as_uint(abuf[r1 + 4]);
        }
        int nts[3] = {nA, nB, nC};
        unsigned int b[3][2];
        #pragma unroll
        for (int i = 0; i < 3; i++) {
            int col = wid * 32 + nts[i] * 8 + grp;
            b[i][0] = __float_as_uint(wbuf[(ks * 8 + thr) * 264 + col]);
            b[i][1] = __float_as_uint(wbuf[(ks * 8 + thr + 4) * 264 + col]);
        }
        #pragma unroll
        for (int mt = 0; mt < 4; mt++)
            #pragma unroll
            for (int i = 0; i < 3; i++)
                mma_tf32(acc[mt][nts[i]], a[mt], b[i]);
    }
}

__global__ __launch_bounds__(256, 2) void k_gru(
    const float* __restrict__ memory,
    const float* __restrict__ bih, const float* __restrict__ bhh)
{
    float* sA0  = smem;
    float* sA1  = smem + 2304;
    float* sW0  = smem + 4608;
    float* sW1  = smem + 13056;
    float* sCnt = smem + 21504;

    const int tid  = threadIdx.x;
    const int lane = tid & 31;
    const int wid  = tid >> 5;
    const int grp  = lane >> 2;
    const int thr  = lane & 3;
    const int n0 = blockIdx.x * 64;
    const int nN = min(64, N_NODES - n0);

    if (tid < 64) sCnt[tid] = (tid < nN) ? g_cnt[n0 + tid] : 0.f;
    __syncthreads();

    #pragma unroll 1
    for (int sweep = 0; sweep < 2; sweep++) {
        float4 acc[4][4];
        #pragma unroll
        for (int mt = 0; mt < 4; mt++)
            #pragma unroll
            for (int nt = 0; nt < 4; nt++) acc[mt][nt] = make_float4(0.f, 0.f, 0.f, 0.f);

        gru_stage(0, sweep, sA0, sW0, sCnt, n0, nN, tid);
        CP_COMMIT();
        CP_WAIT(0);
        __syncthreads();

        #pragma unroll 1
        for (int kc = 0; kc < 8; kc++) {
            float* abuf = (kc & 1) ? sA1 : sA0;
            float* wbuf = (kc & 1) ? sW1 : sW0;
            if (kc < 7) {
                gru_stage(kc + 1, sweep, (kc & 1) ? sA0 : sA1, (kc & 1) ? sW0 : sW1,
                          sCnt, n0, nN, tid);
                CP_COMMIT();
            }
            if (kc < 4) gru_mma3(abuf, wbuf, grp, thr, wid, 0, 1, 2, acc);
            else        gru_mma3(abuf, wbuf, grp, thr, wid, 0, 1, 3, acc);
            if (kc < 7) {
                CP_WAIT(0);
                __syncthreads();
            }
        }
        __syncthreads();

        int j0 = sweep * 64 + wid * 8 + 2 * thr;
        float br0 = __ldg(bih + j0) + __ldg(bhh + j0);
        float br1 = __ldg(bih + j0 + 1) + __ldg(bhh + j0 + 1);
        float bz0 = __ldg(bih + 128 + j0) + __ldg(bhh + 128 + j0);
        float bz1 = __ldg(bih + 128 + j0 + 1) + __ldg(bhh + 128 + j0 + 1);
        float bi0 = __ldg(bih + 256 + j0),      bi1 = __ldg(bih + 256 + j0 + 1);
        float bh0 = __ldg(bhh + 256 + j0),      bh1 = __ldg(bhh + 256 + j0 + 1);

        #pragma unroll
        for (int mt = 0; mt < 4; mt++) {
            #pragma unroll
            for (int half = 0; half < 2; half++) {
                int row = mt * 16 + grp + half * 8;
                if (row < nN) {
                    float rp0 = half ? acc[mt][0].z : acc[mt][0].x;
                    float rp1 = half ? acc[mt][0].w : acc[mt][0].y;
                    float zp0 = half ? acc[mt][1].z : acc[mt][1].x;
                    float zp1 = half ? acc[mt][1].w : acc[mt][1].y;
                    float ip0 = half ? acc[mt][2].z : acc[mt][2].x;
                    float ip1 = half ? acc[mt][2].w : acc[mt][2].y;
                    float hp0 = half ? acc[mt][3].z : acc[mt][3].x;
                    float hp1 = half ? acc[mt][3].w : acc[mt][3].y;

                    float2 hv = *(const float2*)(memory + (size_t)(n0 + row) * 128 + j0);
                    float cnt = sCnt[row];

                    float r0g = sigm(rp0 + br0), r1g = sigm(rp1 + br1);
                    float z0g = sigm(zp0 + bz0), z1g = sigm(zp1 + bz1);
                    float n0g = tanhf(ip0 + bi0 + r0g * (hp0 + bh0));
                    float n1g = tanhf(ip1 + bi1 + r1g * (hp1 + bh1));
                    float2 res;
                    res.x = (cnt > 0.f) ? to_tf32((1.f - z0g) * n0g + z0g * hv.x) : to_tf32(hv.x);
                    res.y = (cnt > 0.f) ? to_tf32((1.f - z1g) * n1g + z1g * hv.y) : to_tf32(hv.y);
                    *(float2*)(g_newmem + (size_t)(n0 + row) * 128 + j0) = res;
                }
            }
        }
    }
}

// ======================= K3: embeddings (R11) ====================================
__device__ __forceinline__ void emb_stage(
    int kc, float* abuf, float* wbuf,
    const int* sN, int nE, int e0, const float* feats, int tid)
{
    if (kc < 4) {
        int q0 = kc * 8;
        #pragma unroll
        for (int it = 0; it < 4; it++) {
            int idx = tid + 256 * it;
            int e = idx >> 3, q = idx & 7;
            cpa16(abuf + e * 36 + q * 4,
                  (const float4*)(g_newmem + (size_t)sN[e] * 128) + q0 + q, e < nE);
        }
    } else {
        int fc = kc - 4;
        #pragma unroll
        for (int it = 0; it < 4; it++) {
            int idx = tid + 256 * it;
            int e = idx >> 3, q = idx & 7;
            float4 v = make_float4(0.f, 0.f, 0.f, 0.f);
            if (e < nE) v = __ldg((const float4*)(feats + (size_t)(e0 + e) * 64) + fc * 8 + q);
            *((float4*)(abuf + e * 36 + q * 4)) = to_tf32_4(v);
        }
    }
    const float4* wsrc = (const float4*)(g_eW1r + (size_t)kc * 32 * 64);
    #pragma unroll
    for (int it = 0; it < 2; it++) {
        int idx = tid + 256 * it;
        int r = idx >> 4, c = idx & 15;
        cpa16(wbuf + r * 72 + c * 4, wsrc + idx, true);
    }
}

__global__ __launch_bounds__(256, 2) void k_emb(
    const int* __restrict__ src, const int* __restrict__ dst,
    const float* __restrict__ sf, const float* __restrict__ df,
    const float* __restrict__ b1,
    float* __restrict__ out, int E)
{
    float* sA0 = smem;
    float* sW0 = smem + 4608;
    float* sHs = smem + 6912;
    float* sHd = smem + 15616;
    float* sA1 = smem + 15616;
    float* sW1 = smem + 20224;
    float* sM  = smem;
    float* sv  = smem + 4096;
    int*   sN  = (int*)(smem + 24320);

    const int tid  = threadIdx.x;
    const int lane = tid & 31;
    const int wid  = tid >> 5;
    const int wm   = wid >> 1;
    const int wn   = wid & 1;
    const int grp  = lane >> 2;
    const int thr  = lane & 3;
    const int e0 = blockIdx.x * 128;
    const int nE = min(128, E - e0);

    #pragma unroll 1
    for (int side = 0; side < 2; side++) {
        const int* nodes = side ? dst : src;
        const float* feats = side ? df : sf;
        float* sH = side ? sHd : sHs;

        __syncthreads();
        if (tid < 128) sN[tid] = (tid < nE) ? nodes[e0 + tid] : 0;
        __syncthreads();

        float4 acc[2][4];
        #pragma unroll
        for (int mt = 0; mt < 2; mt++)
            #pragma unroll
            for (int nt = 0; nt < 4; nt++) acc[mt][nt] = make_float4(0.f, 0.f, 0.f, 0.f);

        emb_stage(0, sA0, sW0, sN, nE, e0, feats, tid);
        CP_COMMIT();
        CP_WAIT(0);
        __syncthreads();

        #pragma unroll 1
        for (int kc = 0; kc < 6; kc++) {
            float* abuf = (kc & 1) ? sA1 : sA0;
            float* wbuf = (kc & 1) ? sW1 : sW0;
            if (kc < 5) {
                emb_stage(kc + 1, (kc & 1) ? sA0 : sA1, (kc & 1) ? sW0 : sW1,
                          sN, nE, e0, feats, tid);
                CP_COMMIT();
            }
            #pragma unroll
            for (int ks = 0; ks < 4; ks++) {
                unsigned int a[2][4], b[4][2];
                #pragma unroll
                for (int mt = 0; mt < 2; mt++) {
                    int r0 = (wm * 32 + mt * 16 + grp) * 36 + ks * 8 + thr;
                    int r1 = r0 + 8 * 36;
                    a[mt][0] = __float_as_uint(abuf[r0]);
                    a[mt][1] = __float_as_uint(abuf[r1]);
                    a[mt][2] = __float_as_uint(abuf[r0 + 4]);
                    a[mt][3] = __float_as_uint(abuf[r1 + 4]);
                }
                #pragma unroll
                for (int nt = 0; nt < 4; nt++) {
                    int col = wn * 32 + nt * 8 + grp;
                    b[nt][0] = __float_as_uint(wbuf[(ks * 8 + thr) * 72 + col]);
                    b[nt][1] = __float_as_uint(wbuf[(ks * 8 + thr + 4) * 72 + col]);
                }
                #pragma unroll
                for (int mt = 0; mt < 2; mt++)
                    #pragma unroll
                    for (int nt = 0; nt < 4; nt++)
                        mma_tf32(acc[mt][nt], a[mt], b[nt]);
            }
            if (kc < 5) {
                CP_WAIT(0);
                __syncthreads();
            }
        }
        __syncthreads();

        {
            float bc0[4], bc1[4];
            #pragma unroll
            for (int nt = 0; nt < 4; nt++) {
                int col = wn * 32 + nt * 8 + 2 * thr;
                bc0[nt] = __ldg(b1 + col);
                bc1[nt] = __ldg(b1 + col + 1);
            }
            #pragma unroll
            for (int mt = 0; mt < 2; mt++) {
                int r0 = wm * 32 + mt * 16 + grp;
                #pragma unroll
                for (int nt = 0; nt < 4; nt++) {
                    int col = wn * 32 + nt * 8 + 2 * thr;
                    sH[r0 * 68 + col]           = fmaxf(acc[mt][nt].x + bc0[nt], 0.f);
                    sH[r0 * 68 + col + 1]       = fmaxf(acc[mt][nt].y + bc1[nt], 0.f);
                    sH[(r0 + 8) * 68 + col]     = fmaxf(acc[mt][nt].z + bc0[nt], 0.f);
                    sH[(r0 + 8) * 68 + col + 1] = fmaxf(acc[mt][nt].w + bc1[nt], 0.f);
                }
            }
        }
    }
    __syncthreads();

    #pragma unroll
    for (int it = 0; it < 4; it++)
        ((float4*)sM)[tid + 256 * it] = ((const float4*)g_M)[tid + 256 * it];
    if (tid < 16) ((float4*)sv)[tid] = ((const float4*)g_v)[tid];
    __syncthreads();

    const int tx = tid & 15, ty = tid >> 4;
    float4 t[8];
    #pragma unroll
    for (int i = 0; i < 8; i++) t[i] = make_float4(0.f, 0.f, 0.f, 0.f);
    #pragma unroll 8
    for (int kk = 0; kk < 64; kk++) {
        float4 m = ((const float4*)sM)[kk * 16 + tx];
        #pragma unroll
        for (int i = 0; i < 8; i++) {
            float a = sHd[(i * 16 + ty) * 68 + kk];
            t[i].x = fmaf(a, m.x, t[i].x);
            t[i].y = fmaf(a, m.y, t[i].y);
            t[i].z = fmaf(a, m.z, t[i].z);
            t[i].w = fmaf(a, m.w, t[i].w);
        }
    }

    float c0 = g_c0;
    float4 vv = ((const float4*)sv)[tx];
    float p[8];
    #pragma unroll
    for (int i = 0; i < 8; i++) {
        int row = i * 16 + ty;
        float4 hs = ((const float4*)(sHs + row * 68))[tx];
        float4 hd = ((const float4*)(sHd + row * 68))[tx];
        p[i] = hs.x * t[i].x + hs.y * t[i].y + hs.z * t[i].z + hs.w * t[i].w
             + (hs.x + hd.x) * vv.x + (hs.y + hd.y) * vv.y
             + (hs.z + hd.z) * vv.z + (hs.w + hd.w) * vv.w;
    }
    #pragma unroll
    for (int m = 1; m < 16; m <<= 1)
        #pragma unroll
        for (int i = 0; i < 8; i++)
            p[i] += __shfl_xor_sync(0xffffffffu, p[i], m);
    if (tx == 0) {
        #pragma unroll
        for (int i = 0; i < 8; i++) {
            int e = i * 16 + ty;
            if (e < nE) out[e0 + e] = p[i] + c0;
        }
    }
}

// ---------------- host launch ----------------
extern "C" void kernel_launch(void* const* d_in, const int* in_sizes, int n_in,
                              void* d_out, int out_size)
{
    const int*   src   = (const int*)d_in[0];
    const int*   dst   = (const int*)d_in[1];
    const float* ef    = (const float*)d_in[2];
    const float* ts    = (const float*)d_in[3];
    const float* sf    = (const float*)d_in[4];
    const float* df    = (const float*)d_in[5];
    const float* mem   = (const float*)d_in[6];
    const float* tw    = (const float*)d_in[7];
    const float* tb    = (const float*)d_in[8];
    const float* mw1   = (const float*)d_in[9];
    const float* mb1   = (const float*)d_in[10];
    const float* mw2   = (const float*)d_in[11];
    const float* mb2   = (const float*)d_in[12];
    const float* gwih  = (const float*)d_in[13];
    const float* gwhh  = (const float*)d_in[14];
    const float* gbih  = (const float*)d_in[15];
    const float* gbhh  = (const float*)d_in[16];
    const float* ew1   = (const float*)d_in[17];
    const float* eb1   = (const float*)d_in[18];
    const float* ew2   = (const float*)d_in[19];
    const float* eb2   = (const float*)d_in[20];
    float* out = (float*)d_out;

    const int E = in_sizes[0];

    const int SMEM1 = (16896 + 2 * 4352) * 4 + 256 * 4;
    const int SMEM2 = (2 * 2304 + 2 * 8448 + 64) * 4;
    const int SMEM3 = 24320 * 4 + 128 * 4;

    cudaFuncSetAttribute(k_msg, cudaFuncAttributeMaxDynamicSharedMemorySize, SMEM1);
    cudaFuncSetAttribute(k_gru, cudaFuncAttributeMaxDynamicSharedMemorySize, SMEM2);
    cudaFuncSetAttribute(k_emb, cudaFuncAttributeMaxDynamicSharedMemorySize, SMEM3);

    k_prep<<<2048, 256>>>(mem, mw1, mw2, ew1, gwih, gwhh);
    k_pre<<<1, 256>>>(ew2, eb2);
    k_msg<<<(E + 127) / 128, 256, SMEM1>>>(src, dst, ef, ts, tw, tb, mb1, mb2, E);
    k_gru<<<(N_NODES + 63) / 64, 256, SMEM2>>>(mem, gbih, gbhh);
    k_emb<<<(E + 127) / 128, 256, SMEM3>>>(src, dst, sf, df, eb1, out, E);
}

// round 15
// speedup vs baseline: 1.1369x; 1.0423x over previous
#include <cuda_runtime.h>
#include <stdint.h>
#include <math.h>

#define N_NODES 100000
#define MEM_DIM 128
#define MSG_DIM 128

// ---------------- scratch (static device globals; no allocation) ----------------
__device__ float g_aggr[(size_t)N_NODES * MSG_DIM];
__device__ float g_cnt[N_NODES];
__device__ float g_newmem[(size_t)N_NODES * MEM_DIM]; // tf32-rounded at write
__device__ float g_memr[(size_t)N_NODES * MEM_DIM];   // tf32-rounded memory
__device__ float g_M[64 * 64];
__device__ float g_v[64];
__device__ float g_c0;
__device__ float g_Wg[256 * 512];  // gate-interleaved GRU weights (tf32)
__device__ float g_W1r[320 * 128]; // msg W1 tf32
__device__ float g_W2r[128 * 128]; // msg W2 tf32
__device__ float g_eW1r[192 * 64]; // emb W1 tf32

extern __shared__ float smem[];

// ---------------- helpers ----------------
__device__ __forceinline__ float to_tf32(float x) {
    unsigned int u;
    asm("cvt.rna.tf32.f32 %0, %1;" : "=r"(u) : "f"(x));
    return __uint_as_float(u);
}
__device__ __forceinline__ float4 to_tf32_4(float4 v) {
    v.x = to_tf32(v.x); v.y = to_tf32(v.y);
    v.z = to_tf32(v.z); v.w = to_tf32(v.w);
    return v;
}
__device__ __forceinline__ void mma_tf32(float4& c, const unsigned int a[4], const unsigned int b[2]) {
    asm volatile(
        "mma.sync.aligned.m16n8k8.row.col.f32.tf32.tf32.f32 "
        "{%0,%1,%2,%3},{%4,%5,%6,%7},{%8,%9},{%0,%1,%2,%3};\n"
        : "+f"(c.x), "+f"(c.y), "+f"(c.z), "+f"(c.w)
        : "r"(a[0]), "r"(a[1]), "r"(a[2]), "r"(a[3]), "r"(b[0]), "r"(b[1]));
}
__device__ __forceinline__ float sigm(float x) { return 1.f / (1.f + expf(-x)); }

__device__ __forceinline__ void cpa16(float* dst, const void* src, bool pred) {
    unsigned sa = (unsigned)__cvta_generic_to_shared(dst);
    asm volatile("cp.async.ca.shared.global [%0], [%1], 16, %2;\n"
                 :: "r"(sa), "l"(src), "r"(pred ? 16 : 0));
}
#define CP_COMMIT() asm volatile("cp.async.commit_group;\n" ::: "memory")
#define CP_WAIT(n)  asm volatile("cp.async.wait_group %0;\n" :: "n"(n) : "memory")

// ---------------- K-prep: zero + tf32 pre-round + GRU weight build ----------------
__global__ void k_prep(const float* __restrict__ memory,
                       const float* __restrict__ W1, const float* __restrict__ W2,
                       const float* __restrict__ eW1,
                       const float* __restrict__ Wih, const float* __restrict__ Whh) {
    size_t stride = (size_t)gridDim.x * blockDim.x;
    size_t t = (size_t)blockIdx.x * blockDim.x + threadIdx.x;
    float4 z = make_float4(0.f, 0.f, 0.f, 0.f);
    for (size_t i = t; i < (size_t)N_NODES * MSG_DIM / 4; i += stride) ((float4*)g_aggr)[i] = z;
    for (size_t i = t; i < N_NODES; i += stride) g_cnt[i] = 0.f;
    for (size_t i = t; i < (size_t)N_NODES * MEM_DIM / 4; i += stride)
        ((float4*)g_memr)[i] = to_tf32_4(__ldg((const float4*)memory + i));
    for (size_t i = t; i < 320 * 128 / 4; i += stride)
        ((float4*)g_W1r)[i] = to_tf32_4(__ldg((const float4*)W1 + i));
    for (size_t i = t; i < 128 * 128 / 4; i += stride)
        ((float4*)g_W2r)[i] = to_tf32_4(__ldg((const float4*)W2 + i));
    for (size_t i = t; i < 192 * 64 / 4; i += stride)
        ((float4*)g_eW1r)[i] = to_tf32_4(__ldg((const float4*)eW1 + i));
    for (size_t p = t; p < 256 * 512; p += stride) {
        int k = (int)(p >> 9), c = (int)(p & 511);
        int jb = c >> 5, tt = c & 31, q = tt >> 3;
        int j = jb * 8 + (tt & 7);
        float w;
        if (q == 0)      w = (k < 128) ? Wih[(size_t)j * 128 + k]
                                       : Whh[(size_t)j * 128 + (k - 128)];
        else if (q == 1) w = (k < 128) ? Wih[(size_t)(128 + j) * 128 + k]
                                       : Whh[(size_t)(128 + j) * 128 + (k - 128)];
        else if (q == 2) w = (k < 128) ? Wih[(size_t)(256 + j) * 128 + k] : 0.f;
        else             w = (k < 128) ? 0.f : Whh[(size_t)(256 + j) * 128 + (k - 128)];
        g_Wg[p] = to_tf32(w);
    }
}

// ---------------- K-pre: bilinear precompute for emb ----------------
__global__ void k_pre(const float* __restrict__ W2, const float* __restrict__ b2) {
    __shared__ float sW2[64 * 64];
    __shared__ float sb2[64];
    int tid = threadIdx.x;
    for (int i = tid; i < 64 * 64; i += 256) sW2[i] = W2[i];
    if (tid < 64) sb2[tid] = b2[tid];
    __syncthreads();
    for (int p = tid; p < 64 * 64; p += 256) {
        int j = p >> 6, k = p & 63;
        float s = 0.f;
        #pragma unroll 16
        for (int c = 0; c < 64; c++) s = fmaf(sW2[j * 64 + c], sW2[k * 64 + c], s);
        g_M[p] = s;
    }
    if (tid < 64) {
        float s = 0.f;
        #pragma unroll 16
        for (int c = 0; c < 64; c++) s = fmaf(sW2[tid * 64 + c], sb2[c], s);
        g_v[tid] = s;
    }
    if (tid == 0) {
        float s = 0.f;
        for (int c = 0; c < 64; c++) s = fmaf(sb2[c], sb2[c], s);
        g_c0 = s;
    }
}

// ======================= K1: message MLP (R14 best) ===============================
__device__ __forceinline__ void msg_stage(
    int kc, float* abuf, float* wbuf,
    const int* sN, int nE, int e0,
    const float* ef, const float* ts,
    const float* tw, const float* tb, int tid)
{
    if (kc < 8) {
        const int* nodes = (kc < 4) ? sN : sN + 128;
        int q0 = (kc & 3) * 8;
        #pragma unroll
        for (int it = 0; it < 4; it++) {
            int idx = tid + 256 * it;
            int e = idx >> 3, q = idx & 7;
            cpa16(abuf + e * 36 + q * 4,
                  (const float4*)(g_memr + (size_t)nodes[e] * 128) + q0 + q, e < nE);
        }
    } else if (kc == 8) {
        #pragma unroll
        for (int it = 0; it < 4; it++) {
            int idx = tid + 256 * it;
            int e = idx >> 3, q = idx & 7;
            float4 v = make_float4(0.f, 0.f, 0.f, 0.f);
            if (e < nE) v = __ldg((const float4*)(ef + (size_t)(e0 + e) * 32) + q);
            *((float4*)(abuf + e * 36 + q * 4)) = to_tf32_4(v);
        }
    } else {
        for (int it = 0; it < 16; it++) {
            int idx = tid + 256 * it;
            int e = idx >> 5, c = idx & 31;
            float t = 0.f;
            if (e < nE) t = cosf(ts[e0 + e] * __ldg(tw + c) + __ldg(tb + c));
            abuf[e * 36 + c] = to_tf32(t);
        }
    }
    const float4* wsrc = (const float4*)(g_W1r + (size_t)kc * 32 * 128);
    #pragma unroll
    for (int it = 0; it < 4; it++) {
        int idx = tid + 256 * it;
        int r = idx >> 5, c = idx & 31;
        cpa16(wbuf + r * 136 + c * 4, wsrc + idx, true);
    }
}
__device__ __forceinline__ void msg_stage_w2(int kc, float* wbuf, int tid) {
    const float4* wsrc = (const float4*)(g_W2r + (size_t)kc * 32 * 128);
    #pragma unroll
    for (int it = 0; it < 4; it++) {
        int idx = tid + 256 * it;
        int r = idx >> 5, c = idx & 31;
        cpa16(wbuf + r * 136 + c * 4, wsrc + idx, true);
    }
}

__global__ __launch_bounds__(256, 2) void k_msg(
    const int* __restrict__ src, const int* __restrict__ dst,
    const float* __restrict__ ef, const float* __restrict__ ts,
    const float* __restrict__ tw, const float* __restrict__ tb,
    const float* __restrict__ b1, const float* __restrict__ b2,
    int E)
{
    float* sU  = smem;
    float* sA0 = smem;
    float* sA1 = smem + 4608;
    float* sWa = smem + 16896;
    float* sWb = sWa + 4352;
    int*   sN  = (int*)(sWb + 4352);

    const int tid  = threadIdx.x;
    const int lane = tid & 31;
    const int wid  = tid >> 5;
    const int wm   = wid >> 2;
    const int wn   = wid & 3;
    const int grp  = lane >> 2;
    const int thr  = lane & 3;
    const int e0 = blockIdx.x * 128;
    const int nE = min(128, E - e0);

    if (tid < 128) sN[tid] = (tid < nE) ? src[e0 + tid] : 0;
    else           sN[tid] = (tid - 128 < nE) ? dst[e0 + tid - 128] : 0;
    __syncthreads();

    float4 acc[4][4];
    #pragma unroll
    for (int mt = 0; mt < 4; mt++)
        #pragma unroll
        for (int nt = 0; nt < 4; nt++) acc[mt][nt] = make_float4(0.f, 0.f, 0.f, 0.f);

    msg_stage(0, sA0, sWa, sN, nE, e0, ef, ts, tw, tb, tid);
    CP_COMMIT();
    CP_WAIT(0);
    __syncthreads();

    #pragma unroll 1
    for (int kc = 0; kc < 10; kc++) {
        float* abuf = (kc & 1) ? sA1 : sA0;
        float* wbuf = (kc & 1) ? sWb : sWa;
        if (kc < 9) {
            msg_stage(kc + 1, (kc & 1) ? sA0 : sA1, (kc & 1) ? sWa : sWb,
                      sN, nE, e0, ef, ts, tw, tb, tid);
            CP_COMMIT();
        }
        #pragma unroll
        for (int ks = 0; ks < 4; ks++) {
            unsigned int a[4][4], b[4][2];
            #pragma unroll
            for (int mt = 0; mt < 4; mt++) {
                int r0 = (wm * 64 + mt * 16 + grp) * 36 + ks * 8 + thr;
                int r1 = r0 + 8 * 36;
                a[mt][0] = __float_as_uint(abuf[r0]);
                a[mt][1] = __float_as_uint(abuf[r1]);
                a[mt][2] = __float_as_uint(abuf[r0 + 4]);
                a[mt][3] = __float_as_uint(abuf[r1 + 4]);
            }
            #pragma unroll
            for (int nt = 0; nt < 4; nt++) {
                int col = wn * 32 + nt * 8 + grp;
                b[nt][0] = __float_as_uint(wbuf[(ks * 8 + thr) * 136 + col]);
                b[nt][1] = __float_as_uint(wbuf[(ks * 8 + thr + 4) * 136 + col]);
            }
            #pragma unroll
            for (int mt = 0; mt < 4; mt++)
                #pragma unroll
                for (int nt = 0; nt < 4; nt++)
                    mma_tf32(acc[mt][nt], a[mt], b[nt]);
        }
        if (kc < 9) {
            CP_WAIT(0);
            __syncthreads();
        }
    }
    __syncthreads();

    msg_stage_w2(0, sWa, tid);
    CP_COMMIT();
    {
        float bc0[4], bc1[4];
        #pragma unroll
        for (int nt = 0; nt < 4; nt++) {
            int col = wn * 32 + nt * 8 + 2 * thr;
            bc0[nt] = __ldg(b1 + col);
            bc1[nt] = __ldg(b1 + col + 1);
        }
        #pragma unroll
        for (int mt = 0; mt < 4; mt++) {
            int r0 = wm * 64 + mt * 16 + grp;
            #pragma unroll
            for (int nt = 0; nt < 4; nt++) {
                int col = wn * 32 + nt * 8 + 2 * thr;
                sU[r0 * 132 + col]           = to_tf32(fmaxf(acc[mt][nt].x + bc0[nt], 0.f));
                sU[r0 * 132 + col + 1]       = to_tf32(fmaxf(acc[mt][nt].y + bc1[nt], 0.f));
                sU[(r0 + 8) * 132 + col]     = to_tf32(fmaxf(acc[mt][nt].z + bc0[nt], 0.f));
                sU[(r0 + 8) * 132 + col + 1] = to_tf32(fmaxf(acc[mt][nt].w + bc1[nt], 0.f));
                acc[mt][nt] = make_float4(0.f, 0.f, 0.f, 0.f);
            }
        }
    }
    CP_WAIT(0);
    __syncthreads();

    #pragma unroll 1
    for (int kc = 0; kc < 4; kc++) {
        float* wbuf = (kc & 1) ? sWb : sWa;
        if (kc < 3) {
            msg_stage_w2(kc + 1, (kc & 1) ? sWa : sWb, tid);
            CP_COMMIT();
        }
        #pragma unroll
        for (int ks = 0; ks < 4; ks++) {
            unsigned int a[4][4], b[4][2];
            int kbase = kc * 32 + ks * 8;
            #pragma unroll
            for (int mt = 0; mt < 4; mt++) {
                int r0 = (wm * 64 + mt * 16 + grp) * 132 + kbase + thr;
                int r1 = r0 + 8 * 132;
                a[mt][0] = __float_as_uint(sU[r0]);
                a[mt][1] = __float_as_uint(sU[r1]);
                a[mt][2] = __float_as_uint(sU[r0 + 4]);
                a[mt][3] = __float_as_uint(sU[r1 + 4]);
            }
            #pragma unroll
            for (int nt = 0; nt < 4; nt++) {
                int col = wn * 32 + nt * 8 + grp;
                b[nt][0] = __float_as_uint(wbuf[(ks * 8 + thr) * 136 + col]);
                b[nt][1] = __float_as_uint(wbuf[(ks * 8 + thr + 4) * 136 + col]);
            }
            #pragma unroll
            for (int mt = 0; mt < 4; mt++)
                #pragma unroll
                for (int nt = 0; nt < 4; nt++)
                    mma_tf32(acc[mt][nt], a[mt], b[nt]);
        }
        if (kc < 3) {
            CP_WAIT(0);
            __syncthreads();
        }
    }
    __syncthreads();

    {
        float bc0[4], bc1[4];
        #pragma unroll
        for (int nt = 0; nt < 4; nt++) {
            int col = wn * 32 + nt * 8 + 2 * thr;
            bc0[nt] = __ldg(b2 + col);
            bc1[nt] = __ldg(b2 + col + 1);
        }
        #pragma unroll
        for (int mt = 0; mt < 4; mt++) {
            int r0 = wm * 64 + mt * 16 + grp;
            #pragma unroll
            for (int nt = 0; nt < 4; nt++) {
                int col = wn * 32 + nt * 8 + 2 * thr;
                sU[r0 * 132 + col]           = acc[mt][nt].x + bc0[nt];
                sU[r0 * 132 + col + 1]       = acc[mt][nt].y + bc1[nt];
                sU[(r0 + 8) * 132 + col]     = acc[mt][nt].z + bc0[nt];
                sU[(r0 + 8) * 132 + col + 1] = acc[mt][nt].w + bc1[nt];
            }
        }
    }
    __syncthreads();

    {
        const int tx = tid & 15, ty = tid >> 4;
        #pragma unroll
        for (int i = 0; i < 8; i++) {
            int e = i * 16 + ty;
            if (e < nE) {
                float4 v0 = ((const float4*)(sU + e * 132))[tx];
                float4 v1 = ((const float4*)(sU + e * 132))[16 + tx];
                int ns = sN[e], nd = sN[128 + e];
                atomicAdd((float4*)(g_aggr + (size_t)ns * 128) + tx, v0);
                atomicAdd((float4*)(g_aggr + (size_t)ns * 128) + 16 + tx, v1);
                atomicAdd((float4*)(g_aggr + (size_t)nd * 128) + tx, v0);
                atomicAdd((float4*)(g_aggr + (size_t)nd * 128) + 16 + tx, v1);
            }
        }
    }
    if (tid < nE) {
        atomicAdd(&g_cnt[sN[tid]], 1.f);
        atomicAdd(&g_cnt[sN[128 + tid]], 1.f);
    }
}

// ======================= K2: GRU (R14 best: zero-pad MMAs skipped) ================
__device__ __forceinline__ void gru_stage(
    int kc, int sweep, float* abuf, float* wbuf,
    const float* sCnt, int n0, int nN, int tid)
{
    #pragma unroll
    for (int it = 0; it < 2; it++) {
        int idx = tid + 256 * it;
        int e = idx >> 3, q = idx & 7;
        if (kc < 4) {
            float4 v = make_float4(0.f, 0.f, 0.f, 0.f);
            if (e < nN) {
                v = *((const float4*)(g_aggr + (size_t)(n0 + e) * 128) + kc * 8 + q);
                float cnt = sCnt[e];
                float inv = (cnt > 0.f) ? (1.f / cnt) : 0.f;
                v.x *= inv; v.y *= inv; v.z *= inv; v.w *= inv;
            }
            *((float4*)(abuf + e * 36 + q * 4)) = to_tf32_4(v);
        } else {
            cpa16(abuf + e * 36 + q * 4,
                  (const float4*)(g_memr + (size_t)(n0 + e) * 128) + (kc - 4) * 8 + q,
                  e < nN);
        }
    }
    const float* wsrc = g_Wg + (size_t)kc * 32 * 512 + sweep * 256;
    #pragma unroll
    for (int it = 0; it < 8; it++) {
        int idx = tid + 256 * it;
        int r = idx >> 6, c = idx & 63;
        int blk = c & 7;
        bool nonzero = (kc < 4) ? (blk < 6) : !(blk == 4 || blk == 5);
        cpa16(wbuf + r * 264 + c * 4,
              (const float4*)(wsrc + (size_t)r * 512) + c, nonzero);
    }
}

__device__ __forceinline__ void gru_mma3(
    const float* abuf, const float* wbuf, int grp, int thr, int wid,
    int nA, int nB, int nC, float4 acc[4][4])
{
    #pragma unroll
    for (int ks = 0; ks < 4; ks++) {
        unsigned int a[4][4];
        #pragma unroll
        for (int mt = 0; mt < 4; mt++) {
            int r0 = (mt * 16 + grp) * 36 + ks * 8 + thr;
            int r1 = r0 + 8 * 36;
            a[mt][0] = __float_as_uint(abuf[r0]);
            a[mt][1] = __float_as_uint(abuf[r1]);
            a[mt][2] = __float_as_uint(abuf[r0 + 4]);
            a[mt][3] = __float_as_uint(abuf[r1 + 4]);
        }
        int nts[3] = {nA, nB, nC};
        unsigned int b[3][2];
        #pragma unroll
        for (int i = 0; i < 3; i++) {
            int col = wid * 32 + nts[i] * 8 + grp;
            b[i][0] = __float_as_uint(wbuf[(ks * 8 + thr) * 264 + col]);
            b[i][1] = __float_as_uint(wbuf[(ks * 8 + thr + 4) * 264 + col]);
        }
        #pragma unroll
        for (int mt = 0; mt < 4; mt++)
            #pragma unroll
            for (int i = 0; i < 3; i++)
                mma_tf32(acc[mt][nts[i]], a[mt], b[i]);
    }
}

__global__ __launch_bounds__(256, 2) void k_gru(
    const float* __restrict__ memory,
    const float* __restrict__ bih, const float* __restrict__ bhh)
{
    float* sA0  = smem;
    float* sA1  = smem + 2304;
    float* sW0  = smem + 4608;
    float* sW1  = smem + 13056;
    float* sCnt = smem + 21504;

    const int tid  = threadIdx.x;
    const int lane = tid & 31;
    const int wid  = tid >> 5;
    const int grp  = lane >> 2;
    const int thr  = lane & 3;
    const int n0 = blockIdx.x * 64;
    const int nN = min(64, N_NODES - n0);

    if (tid < 64) sCnt[tid] = (tid < nN) ? g_cnt[n0 + tid] : 0.f;
    __syncthreads();

    #pragma unroll 1
    for (int sweep = 0; sweep < 2; sweep++) {
        float4 acc[4][4];
        #pragma unroll
        for (int mt = 0; mt < 4; mt++)
            #pragma unroll
            for (int nt = 0; nt < 4; nt++) acc[mt][nt] = make_float4(0.f, 0.f, 0.f, 0.f);

        gru_stage(0, sweep, sA0, sW0, sCnt, n0, nN, tid);
        CP_COMMIT();
        CP_WAIT(0);
        __syncthreads();

        #pragma unroll 1
        for (int kc = 0; kc < 8; kc++) {
            float* abuf = (kc & 1) ? sA1 : sA0;
            float* wbuf = (kc & 1) ? sW1 : sW0;
            if (kc < 7) {
                gru_stage(kc + 1, sweep, (kc & 1) ? sA0 : sA1, (kc & 1) ? sW0 : sW1,
                          sCnt, n0, nN, tid);
                CP_COMMIT();
            }
            if (kc < 4) gru_mma3(abuf, wbuf, grp, thr, wid, 0, 1, 2, acc);
            else        gru_mma3(abuf, wbuf, grp, thr, wid, 0, 1, 3, acc);
            if (kc < 7) {
                CP_WAIT(0);
                __syncthreads();
            }
        }
        __syncthreads();

        int j0 = sweep * 64 + wid * 8 + 2 * thr;
        float br0 = __ldg(bih + j0) + __ldg(bhh + j0);
        float br1 = __ldg(bih + j0 + 1) + __ldg(bhh + j0 + 1);
        float bz0 = __ldg(bih + 128 + j0) + __ldg(bhh + 128 + j0);
        float bz1 = __ldg(bih + 128 + j0 + 1) + __ldg(bhh + 128 + j0 + 1);
        float bi0 = __ldg(bih + 256 + j0),      bi1 = __ldg(bih + 256 + j0 + 1);
        float bh0 = __ldg(bhh + 256 + j0),      bh1 = __ldg(bhh + 256 + j0 + 1);

        #pragma unroll
        for (int mt = 0; mt < 4; mt++) {
            #pragma unroll
            for (int half = 0; half < 2; half++) {
                int row = mt * 16 + grp + half * 8;
                if (row < nN) {
                    float rp0 = half ? acc[mt][0].z : acc[mt][0].x;
                    float rp1 = half ? acc[mt][0].w : acc[mt][0].y;
                    float zp0 = half ? acc[mt][1].z : acc[mt][1].x;
                    float zp1 = half ? acc[mt][1].w : acc[mt][1].y;
                    float ip0 = half ? acc[mt][2].z : acc[mt][2].x;
                    float ip1 = half ? acc[mt][2].w : acc[mt][2].y;
                    float hp0 = half ? acc[mt][3].z : acc[mt][3].x;
                    float hp1 = half ? acc[mt][3].w : acc[mt][3].y;

                    float2 hv = *(const float2*)(memory + (size_t)(n0 + row) * 128 + j0);
                    float cnt = sCnt[row];

                    float r0g = sigm(rp0 + br0), r1g = sigm(rp1 + br1);
                    float z0g = sigm(zp0 + bz0), z1g = sigm(zp1 + bz1);
                    float n0g = tanhf(ip0 + bi0 + r0g * (hp0 + bh0));
                    float n1g = tanhf(ip1 + bi1 + r1g * (hp1 + bh1));
                    float2 res;
                    res.x = (cnt > 0.f) ? to_tf32((1.f - z0g) * n0g + z0g * hv.x) : to_tf32(hv.x);
                    res.y = (cnt > 0.f) ? to_tf32((1.f - z1g) * n1g + z1g * hv.y) : to_tf32(hv.y);
                    *(float2*)(g_newmem + (size_t)(n0 + row) * 128 + j0) = res;
                }
            }
        }
    }
}

// ======================= K3: embeddings, merged M=256 single pass ================
// 128 edges/block, 256 threads. A rows 0..127 = src side, 128..255 = dst side.
// Warps 4x2: wm = wid>>1 (0..3), wn = wid&1. Warp tile 64M x 32N; acc[4][4].
// smem (floats): A0[0,9216) A1[9216,18432) W0[18432,20736) W1[20736,23040)
//   aliases: H @ 0 (256x68 = 17408), M @ 18432 (4096), v @ 22528 (64)
//   sN ints @ 23040 (256)
__device__ __forceinline__ void emb_stage(
    int kc, float* abuf, float* wbuf,
    const int* sN, int nE, int e0,
    const float* sf, const float* df, int tid)
{
    if (kc < 4) {
        int q0 = kc * 8;
        #pragma unroll
        for (int it = 0; it < 8; it++) {
            int idx = tid + 256 * it;
            int e = idx >> 3, q = idx & 7;
            cpa16(abuf + e * 36 + q * 4,
                  (const float4*)(g_newmem + (size_t)sN[e] * 128) + q0 + q, true);
        }
    } else {
        int fc = kc - 4;
        #pragma unroll
        for (int it = 0; it < 8; it++) {
            int idx = tid + 256 * it;
            int e = idx >> 3, q = idx & 7;
            int ee = (e < 128) ? e : e - 128;
            const float* feats = (e < 128) ? sf : df;
            float4 v = make_float4(0.f, 0.f, 0.f, 0.f);
            if (ee < nE) v = __ldg((const float4*)(feats + (size_t)(e0 + ee) * 64) + fc * 8 + q);
            *((float4*)(abuf + e * 36 + q * 4)) = to_tf32_4(v);
        }
    }
    const float4* wsrc = (const float4*)(g_eW1r + (size_t)kc * 32 * 64);
    #pragma unroll
    for (int it = 0; it < 2; it++) {
        int idx = tid + 256 * it;
        int r = idx >> 4, c = idx & 15;
        cpa16(wbuf + r * 72 + c * 4, wsrc + idx, true);
    }
}

__global__ __launch_bounds__(256, 2) void k_emb(
    const int* __restrict__ src, const int* __restrict__ dst,
    const float* __restrict__ sf, const float* __restrict__ df,
    const float* __restrict__ b1,
    float* __restrict__ out, int E)
{
    float* sA0 = smem;
    float* sA1 = smem + 9216;
    float* sW0 = smem + 18432;
    float* sW1 = smem + 20736;
    float* sH  = smem;              // alias (after GEMM1)
    float* sM  = smem + 18432;      // alias (after GEMM1)
    float* sv  = smem + 22528;      // alias
    int*   sN  = (int*)(smem + 23040);

    const int tid  = threadIdx.x;
    const int lane = tid & 31;
    const int wid  = tid >> 5;
    const int wm   = wid >> 1;      // 0..3
    const int wn   = wid & 1;       // 0..1
    const int grp  = lane >> 2;
    const int thr  = lane & 3;
    const int e0 = blockIdx.x * 128;
    const int nE = min(128, E - e0);

    if (tid < 128) sN[tid] = (tid < nE) ? src[e0 + tid] : 0;
    else           sN[tid] = (tid - 128 < nE) ? dst[e0 + tid - 128] : 0;
    __syncthreads();

    float4 acc[4][4];
    #pragma unroll
    for (int mt = 0; mt < 4; mt++)
        #pragma unroll
        for (int nt = 0; nt < 4; nt++) acc[mt][nt] = make_float4(0.f, 0.f, 0.f, 0.f);

    emb_stage(0, sA0, sW0, sN, nE, e0, sf, df, tid);
    CP_COMMIT();
    CP_WAIT(0);
    __syncthreads();

    // GEMM1: M=256, N=64, K=192 in 6 chunks, depth-1 prefetch
    #pragma unroll 1
    for (int kc = 0; kc < 6; kc++) {
        float* abuf = (kc & 1) ? sA1 : sA0;
        float* wbuf = (kc & 1) ? sW1 : sW0;
        if (kc < 5) {
            emb_stage(kc + 1, (kc & 1) ? sA0 : sA1, (kc & 1) ? sW0 : sW1,
                      sN, nE, e0, sf, df, tid);
            CP_COMMIT();
        }
        #pragma unroll
        for (int ks = 0; ks < 4; ks++) {
            unsigned int a[4][4], b[4][2];
            #pragma unroll
            for (int mt = 0; mt < 4; mt++) {
                int r0 = (wm * 64 + mt * 16 + grp) * 36 + ks * 8 + thr;
                int r1 = r0 + 8 * 36;
                a[mt][0] = __float_as_uint(abuf[r0]);
                a[mt][1] = __float_as_uint(abuf[r1]);
                a[mt][2] = __float_as_uint(abuf[r0 + 4]);
                a[mt][3] = __float_as_uint(abuf[r1 + 4]);
            }
            #pragma unroll
            for (int nt = 0; nt < 4; nt++) {
                int col = wn * 32 + nt * 8 + grp;
                b[nt][0] = __float_as_uint(wbuf[(ks * 8 + thr) * 72 + col]);
                b[nt][1] = __float_as_uint(wbuf[(ks * 8 + thr + 4) * 72 + col]);
            }
            #pragma unroll
            for (int mt = 0; mt < 4; mt++)
                #pragma unroll
                for (int nt = 0; nt < 4; nt++)
                    mma_tf32(acc[mt][nt], a[mt], b[nt]);
        }
        if (kc < 5) {
            CP_WAIT(0);
            __syncthreads();
        }
    }
    __syncthreads();   // all fragment reads done; A and W regions now reusable

    // H = relu(acc + b1) -> sH (stride 68); stage M/v into W region
    {
        float bc0[4], bc1[4];
        #pragma unroll
        for (int nt = 0; nt < 4; nt++) {
            int col = wn * 32 + nt * 8 + 2 * thr;
            bc0[nt] = __ldg(b1 + col);
            bc1[nt] = __ldg(b1 + col + 1);
        }
        #pragma unroll
        for (int mt = 0; mt < 4; mt++) {
            int r0 = wm * 64 + mt * 16 + grp;
            #pragma unroll
            for (int nt = 0; nt < 4; nt++) {
                int col = wn * 32 + nt * 8 + 2 * thr;
                sH[r0 * 68 + col]           = fmaxf(acc[mt][nt].x + bc0[nt], 0.f);
                sH[r0 * 68 + col + 1]       = fmaxf(acc[mt][nt].y + bc1[nt], 0.f);
                sH[(r0 + 8) * 68 + col]     = fmaxf(acc[mt][nt].z + bc0[nt], 0.f);
                sH[(r0 + 8) * 68 + col + 1] = fmaxf(acc[mt][nt].w + bc1[nt], 0.f);
            }
        }
    }
    #pragma unroll
    for (int it = 0; it < 4; it++)
        ((float4*)sM)[tid + 256 * it] = ((const float4*)g_M)[tid + 256 * it];
    if (tid < 16) ((float4*)sv)[tid] = ((const float4*)g_v)[tid];
    __syncthreads();

    // bilinear tail: hs = sH rows 0..127, hd = rows 128..255
    const float* sHs = sH;
    const float* sHd = sH + 128 * 68;
    const int tx = tid & 15, ty = tid >> 4;
    float4 t[8];
    #pragma unroll
    for (int i = 0; i < 8; i++) t[i] = make_float4(0.f, 0.f, 0.f, 0.f);
    #pragma unroll 8
    for (int kk = 0; kk < 64; kk++) {
        float4 m = ((const float4*)sM)[kk * 16 + tx];
        #pragma unroll
        for (int i = 0; i < 8; i++) {
            float a = sHd[(i * 16 + ty) * 68 + kk];
            t[i].x = fmaf(a, m.x, t[i].x);
            t[i].y = fmaf(a, m.y, t[i].y);
            t[i].z = fmaf(a, m.z, t[i].z);
            t[i].w = fmaf(a, m.w, t[i].w);
        }
    }

    float c0 = g_c0;
    float4 vv = ((const float4*)sv)[tx];
    float p[8];
    #pragma unroll
    for (int i = 0; i < 8; i++) {
        int row = i * 16 + ty;
        float4 hs = ((const float4*)(sHs + row * 68))[tx];
        float4 hd = ((const float4*)(sHd + row * 68))[tx];
        p[i] = hs.x * t[i].x + hs.y * t[i].y + hs.z * t[i].z + hs.w * t[i].w
             + (hs.x + hd.x) * vv.x + (hs.y + hd.y) * vv.y
             + (hs.z + hd.z) * vv.z + (hs.w + hd.w) * vv.w;
    }
    #pragma unroll
    for (int m = 1; m < 16; m <<= 1)
        #pragma unroll
        for (int i = 0; i < 8; i++)
            p[i] += __shfl_xor_sync(0xffffffffu, p[i], m);
    if (tx == 0) {
        #pragma unroll
        for (int i = 0; i < 8; i++) {
            int e = i * 16 + ty;
            if (e < nE) out[e0 + e] = p[i] + c0;
        }
    }
}

// ---------------- host launch ----------------
extern "C" void kernel_launch(void* const* d_in, const int* in_sizes, int n_in,
                              void* d_out, int out_size)
{
    const int*   src   = (const int*)d_in[0];
    const int*   dst   = (const int*)d_in[1];
    const float* ef    = (const float*)d_in[2];
    const float* ts    = (const float*)d_in[3];
    const float* sf    = (const float*)d_in[4];
    const float* df    = (const float*)d_in[5];
    const float* mem   = (const float*)d_in[6];
    const float* tw    = (const float*)d_in[7];
    const float* tb    = (const float*)d_in[8];
    const float* mw1   = (const float*)d_in[9];
    const float* mb1   = (const float*)d_in[10];
    const float* mw2   = (const float*)d_in[11];
    const float* mb2   = (const float*)d_in[12];
    const float* gwih  = (const float*)d_in[13];
    const float* gwhh  = (const float*)d_in[14];
    const float* gbih  = (const float*)d_in[15];
    const float* gbhh  = (const float*)d_in[16];
    const float* ew1   = (const float*)d_in[17];
    const float* eb1   = (const float*)d_in[18];
    const float* ew2   = (const float*)d_in[19];
    const float* eb2   = (const float*)d_in[20];
    float* out = (float*)d_out;

    const int E = in_sizes[0];

    const int SMEM1 = (16896 + 2 * 4352) * 4 + 256 * 4;
    const int SMEM2 = (2 * 2304 + 2 * 8448 + 64) * 4;
    const int SMEM3 = 23040 * 4 + 256 * 4;   // ~93KB

    cudaFuncSetAttribute(k_msg, cudaFuncAttributeMaxDynamicSharedMemorySize, SMEM1);
    cudaFuncSetAttribute(k_gru, cudaFuncAttributeMaxDynamicSharedMemorySize, SMEM2);
    cudaFuncSetAttribute(k_emb, cudaFuncAttributeMaxDynamicSharedMemorySize, SMEM3);

    k_prep<<<2048, 256>>>(mem, mw1, mw2, ew1, gwih, gwhh);
    k_pre<<<1, 256>>>(ew2, eb2);
    k_msg<<<(E + 127) / 128, 256, SMEM1>>>(src, dst, ef, ts, tw, tb, mb1, mb2, E);
    k_gru<<<(N_NODES + 63) / 64, 256, SMEM2>>>(mem, gbih, gbhh);
    k_emb<<<(E + 127) / 128, 256, SMEM3>>>(src, dst, sf, df, eb1, out, E);
}

// round 16
// speedup vs baseline: 1.1374x; 1.0005x over previous
#include <cuda_runtime.h>
#include <stdint.h>
#include <math.h>

#define N_NODES 100000
#define MEM_DIM 128
#define MSG_DIM 128

// ---------------- scratch (static device globals; no allocation) ----------------
__device__ float g_aggr[(size_t)N_NODES * MSG_DIM];
__device__ float g_cnt[N_NODES];
__device__ float g_newmem[(size_t)N_NODES * MEM_DIM]; // tf32-rounded at write
__device__ float g_memr[(size_t)N_NODES * MEM_DIM];   // tf32-rounded memory
__device__ float g_M[64 * 64];
__device__ float g_v[64];
__device__ float g_c0;
__device__ float g_Wgp[256 * 512];  // GRU weights, k-pair float2 layout (tf32)
__device__ float g_W1p[320 * 128];  // msg W1, k-pair float2 layout (tf32)
__device__ float g_W2p[128 * 128];  // msg W2, k-pair float2 layout (tf32)
__device__ float g_eW1p[192 * 64];  // emb W1, k-pair float2 layout (tf32)

extern __shared__ float smem[];

// ---------------- helpers ----------------
__device__ __forceinline__ float to_tf32(float x) {
    unsigned int u;
    asm("cvt.rna.tf32.f32 %0, %1;" : "=r"(u) : "f"(x));
    return __uint_as_float(u);
}
__device__ __forceinline__ float4 to_tf32_4(float4 v) {
    v.x = to_tf32(v.x); v.y = to_tf32(v.y);
    v.z = to_tf32(v.z); v.w = to_tf32(v.w);
    return v;
}
__device__ __forceinline__ void mma_tf32(float4& c, const unsigned int a[4], const unsigned int b[2]) {
    asm volatile(
        "mma.sync.aligned.m16n8k8.row.col.f32.tf32.tf32.f32 "
        "{%0,%1,%2,%3},{%4,%5,%6,%7},{%8,%9},{%0,%1,%2,%3};\n"
        : "+f"(c.x), "+f"(c.y), "+f"(c.z), "+f"(c.w)
        : "r"(a[0]), "r"(a[1]), "r"(a[2]), "r"(a[3]), "r"(b[0]), "r"(b[1]));
}
__device__ __forceinline__ float sigm(float x) { return 1.f / (1.f + expf(-x)); }

__device__ __forceinline__ void cpa16(float* dst, const void* src, bool pred) {
    unsigned sa = (unsigned)__cvta_generic_to_shared(dst);
    asm volatile("cp.async.ca.shared.global [%0], [%1], 16, %2;\n"
                 :: "r"(sa), "l"(src), "r"(pred ? 16 : 0));
}
#define CP_COMMIT() asm volatile("cp.async.commit_group;\n" ::: "memory")
#define CP_WAIT(n)  asm volatile("cp.async.wait_group %0;\n" :: "n"(n) : "memory")

// ---------------- K-prep: zero + tf32 pre-round + pair-layout weight builds ------
__global__ void k_prep(const float* __restrict__ memory,
                       const float* __restrict__ W1, const float* __restrict__ W2,
                       const float* __restrict__ eW1,
                       const float* __restrict__ Wih, const float* __restrict__ Whh) {
    size_t stride = (size_t)gridDim.x * blockDim.x;
    size_t t = (size_t)blockIdx.x * blockDim.x + threadIdx.x;
    float4 z = make_float4(0.f, 0.f, 0.f, 0.f);
    for (size_t i = t; i < (size_t)N_NODES * MSG_DIM / 4; i += stride) ((float4*)g_aggr)[i] = z;
    for (size_t i = t; i < N_NODES; i += stride) g_cnt[i] = 0.f;
    for (size_t i = t; i < (size_t)N_NODES * MEM_DIM / 4; i += stride)
        ((float4*)g_memr)[i] = to_tf32_4(__ldg((const float4*)memory + i));
    // W1 pair layout: p = ((kc*16+kp)*128 + col)*2 + s ; k = kc*32 + (kp>>2)*8 + (kp&3) + 4s
    for (size_t p = t; p < 320 * 128; p += stride) {
        int s = (int)(p & 1), col = (int)((p >> 1) & 127);
        int kp = (int)((p >> 8) & 15), kc = (int)(p >> 12);
        int k = kc * 32 + (kp >> 2) * 8 + (kp & 3) + 4 * s;
        g_W1p[p] = to_tf32(__ldg(W1 + (size_t)k * 128 + col));
    }
    for (size_t p = t; p < 128 * 128; p += stride) {
        int s = (int)(p & 1), col = (int)((p >> 1) & 127);
        int kp = (int)((p >> 8) & 15), kc = (int)(p >> 12);
        int k = kc * 32 + (kp >> 2) * 8 + (kp & 3) + 4 * s;
        g_W2p[p] = to_tf32(__ldg(W2 + (size_t)k * 128 + col));
    }
    for (size_t p = t; p < 192 * 64; p += stride) {
        int s = (int)(p & 1), col = (int)((p >> 1) & 63);
        int kp = (int)((p >> 7) & 15), kc = (int)(p >> 11);
        int k = kc * 32 + (kp >> 2) * 8 + (kp & 3) + 4 * s;
        g_eW1p[p] = to_tf32(__ldg(eW1 + (size_t)k * 64 + col));
    }
    // GRU gate-interleaved pair layout: p = ((kc*16+kp)*512 + col)*2 + s
    for (size_t p = t; p < 256 * 512; p += stride) {
        int s = (int)(p & 1), col = (int)((p >> 1) & 511);
        int kp = (int)((p >> 10) & 15), kc = (int)(p >> 14);
        int k = kc * 32 + (kp >> 2) * 8 + (kp & 3) + 4 * s;
        int jb = col >> 5, tt = col & 31, q = tt >> 3;
        int j = jb * 8 + (tt & 7);
        float w;
        if (q == 0)      w = (k < 128) ? Wih[(size_t)j * 128 + k]
                                       : Whh[(size_t)j * 128 + (k - 128)];
        else if (q == 1) w = (k < 128) ? Wih[(size_t)(128 + j) * 128 + k]
                                       : Whh[(size_t)(128 + j) * 128 + (k - 128)];
        else if (q == 2) w = (k < 128) ? Wih[(size_t)(256 + j) * 128 + k] : 0.f;
        else             w = (k < 128) ? 0.f : Whh[(size_t)(256 + j) * 128 + (k - 128)];
        g_Wgp[p] = to_tf32(w);
    }
}

// ---------------- K-pre: bilinear precompute for emb ----------------
__global__ void k_pre(const float* __restrict__ W2, const float* __restrict__ b2) {
    __shared__ float sW2[64 * 64];
    __shared__ float sb2[64];
    int tid = threadIdx.x;
    for (int i = tid; i < 64 * 64; i += 256) sW2[i] = W2[i];
    if (tid < 64) sb2[tid] = b2[tid];
    __syncthreads();
    for (int p = tid; p < 64 * 64; p += 256) {
        int j = p >> 6, k = p & 63;
        float s = 0.f;
        #pragma unroll 16
        for (int c = 0; c < 64; c++) s = fmaf(sW2[j * 64 + c], sW2[k * 64 + c], s);
        g_M[p] = s;
    }
    if (tid < 64) {
        float s = 0.f;
        #pragma unroll 16
        for (int c = 0; c < 64; c++) s = fmaf(sW2[tid * 64 + c], sb2[c], s);
        g_v[tid] = s;
    }
    if (tid == 0) {
        float s = 0.f;
        for (int c = 0; c < 64; c++) s = fmaf(sb2[c], sb2[c], s);
        g_c0 = s;
    }
}

// ======================= K1: message MLP (pair-layout W) ==========================
// W smem: 16 kp rows x 128 cols float2, stride 264 (conflict-free LDS.64)
__device__ __forceinline__ void msg_stage(
    int kc, float* abuf, float* wbuf,
    const int* sN, int nE, int e0,
    const float* ef, const float* ts,
    const float* tw, const float* tb, int tid)
{
    if (kc < 8) {
        const int* nodes = (kc < 4) ? sN : sN + 128;
        int q0 = (kc & 3) * 8;
        #pragma unroll
        for (int it = 0; it < 4; it++) {
            int idx = tid + 256 * it;
            int e = idx >> 3, q = idx & 7;
            cpa16(abuf + e * 36 + q * 4,
                  (const float4*)(g_memr + (size_t)nodes[e] * 128) + q0 + q, e < nE);
        }
    } else if (kc == 8) {
        #pragma unroll
        for (int it = 0; it < 4; it++) {
            int idx = tid + 256 * it;
            int e = idx >> 3, q = idx & 7;
            float4 v = make_float4(0.f, 0.f, 0.f, 0.f);
            if (e < nE) v = __ldg((const float4*)(ef + (size_t)(e0 + e) * 32) + q);
            *((float4*)(abuf + e * 36 + q * 4)) = to_tf32_4(v);
        }
    } else {
        for (int it = 0; it < 16; it++) {
            int idx = tid + 256 * it;
            int e = idx >> 5, c = idx & 31;
            float t = 0.f;
            if (e < nE) t = cosf(ts[e0 + e] * __ldg(tw + c) + __ldg(tb + c));
            abuf[e * 36 + c] = to_tf32(t);
        }
    }
    // W1p chunk: 4096 floats = 1024 float4; r = kp, c = float4 (2 cols)
    const float4* wsrc = (const float4*)(g_W1p + (size_t)kc * 4096);
    #pragma unroll
    for (int it = 0; it < 4; it++) {
        int idx = tid + 256 * it;
        int r = idx >> 6, c = idx & 63;
        cpa16(wbuf + r * 264 + c * 4, wsrc + idx, true);
    }
}
__device__ __forceinline__ void msg_stage_w2(int kc, float* wbuf, int tid) {
    const float4* wsrc = (const float4*)(g_W2p + (size_t)kc * 4096);
    #pragma unroll
    for (int it = 0; it < 4; it++) {
        int idx = tid + 256 * it;
        int r = idx >> 6, c = idx & 63;
        cpa16(wbuf + r * 264 + c * 4, wsrc + idx, true);
    }
}

__global__ __launch_bounds__(256, 2) void k_msg(
    const int* __restrict__ src, const int* __restrict__ dst,
    const float* __restrict__ ef, const float* __restrict__ ts,
    const float* __restrict__ tw, const float* __restrict__ tb,
    const float* __restrict__ b1, const float* __restrict__ b2,
    int E)
{
    float* sU  = smem;
    float* sA0 = smem;
    float* sA1 = smem + 4608;
    float* sWa = smem + 16896;
    float* sWb = sWa + 4352;
    int*   sN  = (int*)(sWb + 4352);

    const int tid  = threadIdx.x;
    const int lane = tid & 31;
    const int wid  = tid >> 5;
    const int wm   = wid >> 2;
    const int wn   = wid & 3;
    const int grp  = lane >> 2;
    const int thr  = lane & 3;
    const int e0 = blockIdx.x * 128;
    const int nE = min(128, E - e0);

    if (tid < 128) sN[tid] = (tid < nE) ? src[e0 + tid] : 0;
    else           sN[tid] = (tid - 128 < nE) ? dst[e0 + tid - 128] : 0;
    __syncthreads();

    float4 acc[4][4];
    #pragma unroll
    for (int mt = 0; mt < 4; mt++)
        #pragma unroll
        for (int nt = 0; nt < 4; nt++) acc[mt][nt] = make_float4(0.f, 0.f, 0.f, 0.f);

    msg_stage(0, sA0, sWa, sN, nE, e0, ef, ts, tw, tb, tid);
    CP_COMMIT();
    CP_WAIT(0);
    __syncthreads();

    #pragma unroll 1
    for (int kc = 0; kc < 10; kc++) {
        float* abuf = (kc & 1) ? sA1 : sA0;
        float* wbuf = (kc & 1) ? sWb : sWa;
        if (kc < 9) {
            msg_stage(kc + 1, (kc & 1) ? sA0 : sA1, (kc & 1) ? sWa : sWb,
                      sN, nE, e0, ef, ts, tw, tb, tid);
            CP_COMMIT();
        }
        #pragma unroll
        for (int ks = 0; ks < 4; ks++) {
            unsigned int a[4][4], b[4][2];
            #pragma unroll
            for (int mt = 0; mt < 4; mt++) {
                int r0 = (wm * 64 + mt * 16 + grp) * 36 + ks * 8 + thr;
                int r1 = r0 + 8 * 36;
                a[mt][0] = __float_as_uint(abuf[r0]);
                a[mt][1] = __float_as_uint(abuf[r1]);
                a[mt][2] = __float_as_uint(abuf[r0 + 4]);
                a[mt][3] = __float_as_uint(abuf[r1 + 4]);
            }
            #pragma unroll
            for (int nt = 0; nt < 4; nt++) {
                int col = wn * 32 + nt * 8 + grp;
                float2 bv = *(const float2*)(wbuf + (ks * 4 + thr) * 264 + 2 * col);
                b[nt][0] = __float_as_uint(bv.x);
                b[nt][1] = __float_as_uint(bv.y);
            }
            #pragma unroll
            for (int mt = 0; mt < 4; mt++)
                #pragma unroll
                for (int nt = 0; nt < 4; nt++)
                    mma_tf32(acc[mt][nt], a[mt], b[nt]);
        }
        if (kc < 9) {
            CP_WAIT(0);
            __syncthreads();
        }
    }
    __syncthreads();

    msg_stage_w2(0, sWa, tid);
    CP_COMMIT();
    {
        float bc0[4], bc1[4];
        #pragma unroll
        for (int nt = 0; nt < 4; nt++) {
            int col = wn * 32 + nt * 8 + 2 * thr;
            bc0[nt] = __ldg(b1 + col);
            bc1[nt] = __ldg(b1 + col + 1);
        }
        #pragma unroll
        for (int mt = 0; mt < 4; mt++) {
            int r0 = wm * 64 + mt * 16 + grp;
            #pragma unroll
            for (int nt = 0; nt < 4; nt++) {
                int col = wn * 32 + nt * 8 + 2 * thr;
                sU[r0 * 132 + col]           = to_tf32(fmaxf(acc[mt][nt].x + bc0[nt], 0.f));
                sU[r0 * 132 + col + 1]       = to_tf32(fmaxf(acc[mt][nt].y + bc1[nt], 0.f));
                sU[(r0 + 8) * 132 + col]     = to_tf32(fmaxf(acc[mt][nt].z + bc0[nt], 0.f));
                sU[(r0 + 8) * 132 + col + 1] = to_tf32(fmaxf(acc[mt][nt].w + bc1[nt], 0.f));
                acc[mt][nt] = make_float4(0.f, 0.f, 0.f, 0.f);
            }
        }
    }
    CP_WAIT(0);
    __syncthreads();

    #pragma unroll 1
    for (int kc = 0; kc < 4; kc++) {
        float* wbuf = (kc & 1) ? sWb : sWa;
        if (kc < 3) {
            msg_stage_w2(kc + 1, (kc & 1) ? sWa : sWb, tid);
            CP_COMMIT();
        }
        #pragma unroll
        for (int ks = 0; ks < 4; ks++) {
            unsigned int a[4][4], b[4][2];
            int kbase = kc * 32 + ks * 8;
            #pragma unroll
            for (int mt = 0; mt < 4; mt++) {
                int r0 = (wm * 64 + mt * 16 + grp) * 132 + kbase + thr;
                int r1 = r0 + 8 * 132;
                a[mt][0] = __float_as_uint(sU[r0]);
                a[mt][1] = __float_as_uint(sU[r1]);
                a[mt][2] = __float_as_uint(sU[r0 + 4]);
                a[mt][3] = __float_as_uint(sU[r1 + 4]);
            }
            #pragma unroll
            for (int nt = 0; nt < 4; nt++) {
                int col = wn * 32 + nt * 8 + grp;
                float2 bv = *(const float2*)(wbuf + (ks * 4 + thr) * 264 + 2 * col);
                b[nt][0] = __float_as_uint(bv.x);
                b[nt][1] = __float_as_uint(bv.y);
            }
            #pragma unroll
            for (int mt = 0; mt < 4; mt++)
                #pragma unroll
                for (int nt = 0; nt < 4; nt++)
                    mma_tf32(acc[mt][nt], a[mt], b[nt]);
        }
        if (kc < 3) {
            CP_WAIT(0);
            __syncthreads();
        }
    }
    __syncthreads();

    {
        float bc0[4], bc1[4];
        #pragma unroll
        for (int nt = 0; nt < 4; nt++) {
            int col = wn * 32 + nt * 8 + 2 * thr;
            bc0[nt] = __ldg(b2 + col);
            bc1[nt] = __ldg(b2 + col + 1);
        }
        #pragma unroll
        for (int mt = 0; mt < 4; mt++) {
            int r0 = wm * 64 + mt * 16 + grp;
            #pragma unroll
            for (int nt = 0; nt < 4; nt++) {
                int col = wn * 32 + nt * 8 + 2 * thr;
                sU[r0 * 132 + col]           = acc[mt][nt].x + bc0[nt];
                sU[r0 * 132 + col + 1]       = acc[mt][nt].y + bc1[nt];
                sU[(r0 + 8) * 132 + col]     = acc[mt][nt].z + bc0[nt];
                sU[(r0 + 8) * 132 + col + 1] = acc[mt][nt].w + bc1[nt];
            }
        }
    }
    __syncthreads();

    {
        const int tx = tid & 15, ty = tid >> 4;
        #pragma unroll
        for (int i = 0; i < 8; i++) {
            int e = i * 16 + ty;
            if (e < nE) {
                float4 v0 = ((const float4*)(sU + e * 132))[tx];
                float4 v1 = ((const float4*)(sU + e * 132))[16 + tx];
                int ns = sN[e], nd = sN[128 + e];
                atomicAdd((float4*)(g_aggr + (size_t)ns * 128) + tx, v0);
                atomicAdd((float4*)(g_aggr + (size_t)ns * 128) + 16 + tx, v1);
                atomicAdd((float4*)(g_aggr + (size_t)nd * 128) + tx, v0);
                atomicAdd((float4*)(g_aggr + (size_t)nd * 128) + 16 + tx, v1);
            }
        }
    }
    if (tid < nE) {
        atomicAdd(&g_cnt[sN[tid]], 1.f);
        atomicAdd(&g_cnt[sN[128 + tid]], 1.f);
    }
}

// ======================= K2: GRU (pair-layout W, zero-skip) =======================
// W smem: 16 kp x 256 cols float2, stride 520 (conflict-free LDS.64)
__device__ __forceinline__ void gru_stage(
    int kc, int sweep, float* abuf, float* wbuf,
    const float* sCnt, int n0, int nN, int tid)
{
    #pragma unroll
    for (int it = 0; it < 2; it++) {
        int idx = tid + 256 * it;
        int e = idx >> 3, q = idx & 7;
        if (kc < 4) {
            float4 v = make_float4(0.f, 0.f, 0.f, 0.f);
            if (e < nN) {
                v = *((const float4*)(g_aggr + (size_t)(n0 + e) * 128) + kc * 8 + q);
                float cnt = sCnt[e];
                float inv = (cnt > 0.f) ? (1.f / cnt) : 0.f;
                v.x *= inv; v.y *= inv; v.z *= inv; v.w *= inv;
            }
            *((float4*)(abuf + e * 36 + q * 4)) = to_tf32_4(v);
        } else {
            cpa16(abuf + e * 36 + q * 4,
                  (const float4*)(g_memr + (size_t)(n0 + e) * 128) + (kc - 4) * 8 + q,
                  e < nN);
        }
    }
    // W pair chunk: 16 kp x 256 cols float2 = 2048 float4; r = kp, c = float4 (2 cols)
    #pragma unroll
    for (int it = 0; it < 8; it++) {
        int idx = tid + 256 * it;
        int r = idx >> 7, c = idx & 127;
        int q = (c & 15) >> 2;   // gate block of cols 2c,2c+1 (within 32-col group)
        bool nonzero = (kc < 4) ? (q < 3) : (q != 2);
        const float* wsrc = g_Wgp + (size_t)kc * 16384 + (size_t)r * 1024
                          + sweep * 512 + c * 4;
        cpa16(wbuf + r * 520 + c * 4, wsrc, nonzero);
    }
}

__device__ __forceinline__ void gru_mma3(
    const float* abuf, const float* wbuf, int grp, int thr, int wid,
    int nA, int nB, int nC, float4 acc[4][4])
{
    #pragma unroll
    for (int ks = 0; ks < 4; ks++) {
        unsigned int a[4][4];
        #pragma unroll
        for (int mt = 0; mt < 4; mt++) {
            int r0 = (mt * 16 + grp) * 36 + ks * 8 + thr;
            int r1 = r0 + 8 * 36;
            a[mt][0] = __float_as_uint(abuf[r0]);
            a[mt][1] = __float_as_uint(abuf[r1]);
            a[mt][2] = __float_as_uint(abuf[r0 + 4]);
            a[mt][3] = __float_as_uint(abuf[r1 + 4]);
        }
        int nts[3] = {nA, nB, nC};
        unsigned int b[3][2];
        #pragma unroll
        for (int i = 0; i < 3; i++) {
            int col = wid * 32 + nts[i] * 8 + grp;
            float2 bv = *(const float2*)(wbuf + (ks * 4 + thr) * 520 + 2 * col);
            b[i][0] = __float_as_uint(bv.x);
            b[i][1] = __float_as_uint(bv.y);
        }
        #pragma unroll
        for (int mt = 0; mt < 4; mt++)
            #pragma unroll
            for (int i = 0; i < 3; i++)
                mma_tf32(acc[mt][nts[i]], a[mt], b[i]);
    }
}

__global__ __launch_bounds__(256, 2) void k_gru(
    const float* __restrict__ memory,
    const float* __restrict__ bih, const float* __restrict__ bhh)
{
    float* sA0  = smem;
    float* sA1  = smem + 2304;
    float* sW0  = smem + 4608;
    float* sW1  = smem + 13056;
    float* sCnt = smem + 21504;

    const int tid  = threadIdx.x;
    const int lane = tid & 31;
    const int wid  = tid >> 5;
    const int grp  = lane >> 2;
    const int thr  = lane & 3;
    const int n0 = blockIdx.x * 64;
    const int nN = min(64, N_NODES - n0);

    if (tid < 64) sCnt[tid] = (tid < nN) ? g_cnt[n0 + tid] : 0.f;
    __syncthreads();

    #pragma unroll 1
    for (int sweep = 0; sweep < 2; sweep++) {
        float4 acc[4][4];
        #pragma unroll
        for (int mt = 0; mt < 4; mt++)
            #pragma unroll
            for (int nt = 0; nt < 4; nt++) acc[mt][nt] = make_float4(0.f, 0.f, 0.f, 0.f);

        gru_stage(0, sweep, sA0, sW0, sCnt, n0, nN, tid);
        CP_COMMIT();
        CP_WAIT(0);
        __syncthreads();

        #pragma unroll 1
        for (int kc = 0; kc < 8; kc++) {
            float* abuf = (kc & 1) ? sA1 : sA0;
            float* wbuf = (kc & 1) ? sW1 : sW0;
            if (kc < 7) {
                gru_stage(kc + 1, sweep, (kc & 1) ? sA0 : sA1, (kc & 1) ? sW0 : sW1,
                          sCnt, n0, nN, tid);
                CP_COMMIT();
            }
            if (kc < 4) gru_mma3(abuf, wbuf, grp, thr, wid, 0, 1, 2, acc);
            else        gru_mma3(abuf, wbuf, grp, thr, wid, 0, 1, 3, acc);
            if (kc < 7) {
                CP_WAIT(0);
                __syncthreads();
            }
        }
        __syncthreads();

        int j0 = sweep * 64 + wid * 8 + 2 * thr;
        float br0 = __ldg(bih + j0) + __ldg(bhh + j0);
        float br1 = __ldg(bih + j0 + 1) + __ldg(bhh + j0 + 1);
        float bz0 = __ldg(bih + 128 + j0) + __ldg(bhh + 128 + j0);
        float bz1 = __ldg(bih + 128 + j0 + 1) + __ldg(bhh + 128 + j0 + 1);
        float bi0 = __ldg(bih + 256 + j0),      bi1 = __ldg(bih + 256 + j0 + 1);
        float bh0 = __ldg(bhh + 256 + j0),      bh1 = __ldg(bhh + 256 + j0 + 1);

        #pragma unroll
        for (int mt = 0; mt < 4; mt++) {
            #pragma unroll
            for (int half = 0; half < 2; half++) {
                int row = mt * 16 + grp + half * 8;
                if (row < nN) {
                    float rp0 = half ? acc[mt][0].z : acc[mt][0].x;
                    float rp1 = half ? acc[mt][0].w : acc[mt][0].y;
                    float zp0 = half ? acc[mt][1].z : acc[mt][1].x;
                    float zp1 = half ? acc[mt][1].w : acc[mt][1].y;
                    float ip0 = half ? acc[mt][2].z : acc[mt][2].x;
                    float ip1 = half ? acc[mt][2].w : acc[mt][2].y;
                    float hp0 = half ? acc[mt][3].z : acc[mt][3].x;
                    float hp1 = half ? acc[mt][3].w : acc[mt][3].y;

                    float2 hv = *(const float2*)(memory + (size_t)(n0 + row) * 128 + j0);
                    float cnt = sCnt[row];

                    float r0g = sigm(rp0 + br0), r1g = sigm(rp1 + br1);
                    float z0g = sigm(zp0 + bz0), z1g = sigm(zp1 + bz1);
                    float n0g = tanhf(ip0 + bi0 + r0g * (hp0 + bh0));
                    float n1g = tanhf(ip1 + bi1 + r1g * (hp1 + bh1));
                    float2 res;
                    res.x = (cnt > 0.f) ? to_tf32((1.f - z0g) * n0g + z0g * hv.x) : to_tf32(hv.x);
                    res.y = (cnt > 0.f) ? to_tf32((1.f - z1g) * n1g + z1g * hv.y) : to_tf32(hv.y);
                    *(float2*)(g_newmem + (size_t)(n0 + row) * 128 + j0) = res;
                }
            }
        }
    }
}

// ======================= K3: embeddings, merged M=256 (pair-layout W) =============
// W smem: 16 kp x 64 cols float2, stride 136
__device__ __forceinline__ void emb_stage(
    int kc, float* abuf, float* wbuf,
    const int* sN, int nE, int e0,
    const float* sf, const float* df, int tid)
{
    if (kc < 4) {
        int q0 = kc * 8;
        #pragma unroll
        for (int it = 0; it < 8; it++) {
            int idx = tid + 256 * it;
            int e = idx >> 3, q = idx & 7;
            cpa16(abuf + e * 36 + q * 4,
                  (const float4*)(g_newmem + (size_t)sN[e] * 128) + q0 + q, true);
        }
    } else {
        int fc = kc - 4;
        #pragma unroll
        for (int it = 0; it < 8; it++) {
            int idx = tid + 256 * it;
            int e = idx >> 3, q = idx & 7;
            int ee = (e < 128) ? e : e - 128;
            const float* feats = (e < 128) ? sf : df;
            float4 v = make_float4(0.f, 0.f, 0.f, 0.f);
            if (ee < nE) v = __ldg((const float4*)(feats + (size_t)(e0 + ee) * 64) + fc * 8 + q);
            *((float4*)(abuf + e * 36 + q * 4)) = to_tf32_4(v);
        }
    }
    // eW1p chunk: 2048 floats = 512 float4; r = kp, c covers 2 cols
    const float4* wsrc = (const float4*)(g_eW1p + (size_t)kc * 2048);
    #pragma unroll
    for (int it = 0; it < 2; it++) {
        int idx = tid + 256 * it;
        int r = idx >> 5, c = idx & 31;
        cpa16(wbuf + r * 136 + c * 4, wsrc + idx, true);
    }
}

__global__ __launch_bounds__(256, 2) void k_emb(
    const int* __restrict__ src, const int* __restrict__ dst,
    const float* __restrict__ sf, const float* __restrict__ df,
    const float* __restrict__ b1,
    float* __restrict__ out, int E)
{
    float* sA0 = smem;
    float* sA1 = smem + 9216;
    float* sW0 = smem + 18432;
    float* sW1 = smem + 20736;
    float* sH  = smem;              // alias (after GEMM1)
    float* sM  = smem + 18432;      // alias (after GEMM1)
    float* sv  = smem + 22528;      // alias
    int*   sN  = (int*)(smem + 23040);

    const int tid  = threadIdx.x;
    const int lane = tid & 31;
    const int wid  = tid >> 5;
    const int wm   = wid >> 1;
    const int wn   = wid & 1;
    const int grp  = lane >> 2;
    const int thr  = lane & 3;
    const int e0 = blockIdx.x * 128;
    const int nE = min(128, E - e0);

    if (tid < 128) sN[tid] = (tid < nE) ? src[e0 + tid] : 0;
    else           sN[tid] = (tid - 128 < nE) ? dst[e0 + tid - 128] : 0;
    __syncthreads();

    float4 acc[4][4];
    #pragma unroll
    for (int mt = 0; mt < 4; mt++)
        #pragma unroll
        for (int nt = 0; nt < 4; nt++) acc[mt][nt] = make_float4(0.f, 0.f, 0.f, 0.f);

    emb_stage(0, sA0, sW0, sN, nE, e0, sf, df, tid);
    CP_COMMIT();
    CP_WAIT(0);
    __syncthreads();

    #pragma unroll 1
    for (int kc = 0; kc < 6; kc++) {
        float* abuf = (kc & 1) ? sA1 : sA0;
        float* wbuf = (kc & 1) ? sW1 : sW0;
        if (kc < 5) {
            emb_stage(kc + 1, (kc & 1) ? sA0 : sA1, (kc & 1) ? sW0 : sW1,
                      sN, nE, e0, sf, df, tid);
            CP_COMMIT();
        }
        #pragma unroll
        for (int ks = 0; ks < 4; ks++) {
            unsigned int a[4][4], b[4][2];
            #pragma unroll
            for (int mt = 0; mt < 4; mt++) {
                int r0 = (wm * 64 + mt * 16 + grp) * 36 + ks * 8 + thr;
                int r1 = r0 + 8 * 36;
                a[mt][0] = __float_as_uint(abuf[r0]);
                a[mt][1] = __float_as_uint(abuf[r1]);
                a[mt][2] = __float_as_uint(abuf[r0 + 4]);
                a[mt][3] = __float_as_uint(abuf[r1 + 4]);
            }
            #pragma unroll
            for (int nt = 0; nt < 4; nt++) {
                int col = wn * 32 + nt * 8 + grp;
                float2 bv = *(const float2*)(wbuf + (ks * 4 + thr) * 136 + 2 * col);
                b[nt][0] = __float_as_uint(bv.x);
                b[nt][1] = __float_as_uint(bv.y);
            }
            #pragma unroll
            for (int mt = 0; mt < 4; mt++)
                #pragma unroll
                for (int nt = 0; nt < 4; nt++)
                    mma_tf32(acc[mt][nt], a[mt], b[nt]);
        }
        if (kc < 5) {
            CP_WAIT(0);
            __syncthreads();
        }
    }
    __syncthreads();

    {
        float bc0[4], bc1[4];
        #pragma unroll
        for (int nt = 0; nt < 4; nt++) {
            int col = wn * 32 + nt * 8 + 2 * thr;
            bc0[nt] = __ldg(b1 + col);
            bc1[nt] = __ldg(b1 + col + 1);
        }
        #pragma unroll
        for (int mt = 0; mt < 4; mt++) {
            int r0 = wm * 64 + mt * 16 + grp;
            #pragma unroll
            for (int nt = 0; nt < 4; nt++) {
                int col = wn * 32 + nt * 8 + 2 * thr;
                sH[r0 * 68 + col]           = fmaxf(acc[mt][nt].x + bc0[nt], 0.f);
                sH[r0 * 68 + col + 1]       = fmaxf(acc[mt][nt].y + bc1[nt], 0.f);
                sH[(r0 + 8) * 68 + col]     = fmaxf(acc[mt][nt].z + bc0[nt], 0.f);
                sH[(r0 + 8) * 68 + col + 1] = fmaxf(acc[mt][nt].w + bc1[nt], 0.f);
            }
        }
    }
    #pragma unroll
    for (int it = 0; it < 4; it++)
        ((float4*)sM)[tid + 256 * it] = ((const float4*)g_M)[tid + 256 * it];
    if (tid < 16) ((float4*)sv)[tid] = ((const float4*)g_v)[tid];
    __syncthreads();

    const float* sHs = sH;
    const float* sHd = sH + 128 * 68;
    const int tx = tid & 15, ty = tid >> 4;
    float4 t[8];
    #pragma unroll
    for (int i = 0; i < 8; i++) t[i] = make_float4(0.f, 0.f, 0.f, 0.f);
    #pragma unroll 8
    for (int kk = 0; kk < 64; kk++) {
        float4 m = ((const float4*)sM)[kk * 16 + tx];
        #pragma unroll
        for (int i = 0; i < 8; i++) {
            float a = sHd[(i * 16 + ty) * 68 + kk];
            t[i].x = fmaf(a, m.x, t[i].x);
            t[i].y = fmaf(a, m.y, t[i].y);
            t[i].z = fmaf(a, m.z, t[i].z);
            t[i].w = fmaf(a, m.w, t[i].w);
        }
    }

    float c0 = g_c0;
    float4 vv = ((const float4*)sv)[tx];
    float p[8];
    #pragma unroll
    for (int i = 0; i < 8; i++) {
        int row = i * 16 + ty;
        float4 hs = ((const float4*)(sHs + row * 68))[tx];
        float4 hd = ((const float4*)(sHd + row * 68))[tx];
        p[i] = hs.x * t[i].x + hs.y * t[i].y + hs.z * t[i].z + hs.w * t[i].w
             + (hs.x + hd.x) * vv.x + (hs.y + hd.y) * vv.y
             + (hs.z + hd.z) * vv.z + (hs.w + hd.w) * vv.w;
    }
    #pragma unroll
    for (int m = 1; m < 16; m <<= 1)
        #pragma unroll
        for (int i = 0; i < 8; i++)
            p[i] += __shfl_xor_sync(0xffffffffu, p[i], m);
    if (tx == 0) {
        #pragma unroll
        for (int i = 0; i < 8; i++) {
            int e = i * 16 + ty;
            if (e < nE) out[e0 + e] = p[i] + c0;
        }
    }
}

// ---------------- host launch ----------------
extern "C" void kernel_launch(void* const* d_in, const int* in_sizes, int n_in,
                              void* d_out, int out_size)
{
    const int*   src   = (const int*)d_in[0];
    const int*   dst   = (const int*)d_in[1];
    const float* ef    = (const float*)d_in[2];
    const float* ts    = (const float*)d_in[3];
    const float* sf    = (const float*)d_in[4];
    const float* df    = (const float*)d_in[5];
    const float* mem   = (const float*)d_in[6];
    const float* tw    = (const float*)d_in[7];
    const float* tb    = (const float*)d_in[8];
    const float* mw1   = (const float*)d_in[9];
    const float* mb1   = (const float*)d_in[10];
    const float* mw2   = (const float*)d_in[11];
    const float* mb2   = (const float*)d_in[12];
    const float* gwih  = (const float*)d_in[13];
    const float* gwhh  = (const float*)d_in[14];
    const float* gbih  = (const float*)d_in[15];
    const float* gbhh  = (const float*)d_in[16];
    const float* ew1   = (const float*)d_in[17];
    const float* eb1   = (const float*)d_in[18];
    const float* ew2   = (const float*)d_in[19];
    const float* eb2   = (const float*)d_in[20];
    float* out = (float*)d_out;

    const int E = in_sizes[0];

    const int SMEM1 = (16896 + 2 * 4352) * 4 + 256 * 4;
    const int SMEM2 = (2 * 2304 + 2 * 8448 + 64) * 4;
    const int SMEM3 = 23040 * 4 + 256 * 4;

    cudaFuncSetAttribute(k_msg, cudaFuncAttributeMaxDynamicSharedMemorySize, SMEM1);
    cudaFuncSetAttribute(k_gru, cudaFuncAttributeMaxDynamicSharedMemorySize, SMEM2);
    cudaFuncSetAttribute(k_emb, cudaFuncAttributeMaxDynamicSharedMemorySize, SMEM3);

    k_prep<<<2048, 256>>>(mem, mw1, mw2, ew1, gwih, gwhh);
    k_pre<<<1, 256>>>(ew2, eb2);
    k_msg<<<(E + 127) / 128, 256, SMEM1>>>(src, dst, ef, ts, tw, tb, mb1, mb2, E);
    k_gru<<<(N_NODES + 63) / 64, 256, SMEM2>>>(mem, gbih, gbhh);
    k_emb<<<(E + 127) / 128, 256, SMEM3>>>(src, dst, sf, df, eb1, out, E);
}